// round 11
// baseline (speedup 1.0000x reference)
#include <cuda_runtime.h>

#define NB 8
#define NN 10000
#define CI 16
#define TT 24
#define CO 32
#define NE 160000
#define BT 192   // NB*TT

// ---------------- device scratch (float4-typed => 16B alignment) ----------------
__device__ float4 g_X0[(size_t)NN * BT * CI / 4];   // 123 MB layer-1 input (node-major)
__device__ float4 g_A0[(size_t)NN * BT * CI / 4];   // 123 MB layer-1 aggregated
__device__ float4 g_Y1[(size_t)NN * BT * CO / 4];   // 246 MB layer-1 output
__device__ float4 g_A1[(size_t)NN * BT * CO / 4];   // 246 MB layer-2 aggregated
__device__ int    g_rowptr[NN + 1];
__device__ int    g_col[NE];
__device__ int    g_is64;

// ---------------- weights in constant memory (uniform port, off the smem crossbar) ----------------
__constant__ float c_W1[CI * 64];
__constant__ float c_b1[64];
__constant__ float c_W2[64 * CO];
__constant__ float c_b2[CO];
__constant__ float c_W3[CO * 128];
__constant__ float c_b3[128];
__constant__ float c_W4[128 * CO];
__constant__ float c_b4[CO];

// ---------------- packed f32x2 helpers ----------------
__device__ __forceinline__ unsigned long long fma2(unsigned long long a,
                                                   unsigned long long b,
                                                   unsigned long long c) {
    unsigned long long d;
    asm("fma.rn.f32x2 %0, %1, %2, %3;" : "=l"(d) : "l"(a), "l"(b), "l"(c));
    return d;
}
__device__ __forceinline__ unsigned long long pk2(float x, float y) {
    unsigned long long r;
    asm("mov.b64 %0, {%1, %2};" : "=l"(r) : "f"(x), "f"(y));
    return r;
}
__device__ __forceinline__ float2 upk2(unsigned long long a) {
    float2 r;
    asm("mov.b64 {%0, %1}, %2;" : "=f"(r.x), "=f"(r.y) : "l"(a));
    return r;
}

__device__ __forceinline__ int edge_at(const void* ei, int idx) {
    if (g_is64) return (int)((const long long*)ei)[idx];
    return ((const int*)ei)[idx];
}

// ---------------- CSR prep+fill: detect + histogram + scan + fill, ONE block ----------------
__global__ void __launch_bounds__(1024) k_prepfill(const void* ei) {
    __shared__ int sdeg[NN];    // degree, then reused as fill cursor
    __shared__ int ssum[1024];
    int tid = threadIdx.x;
    if (tid == 0) {  // int64 indices all in [0,NN); int32-reinterpreted are not
        const long long* p = (const long long*)ei;
        int ok64 = 1;
        for (int q = 0; q < 64; q++) {
            long long v = p[q];
            if (v < 0 || v >= NN) { ok64 = 0; break; }
        }
        g_is64 = ok64;
    }
    __syncthreads();
    for (int i = tid; i < NN; i += 1024) sdeg[i] = 0;
    __syncthreads();
    for (int e = tid; e < NE; e += 1024) atomicAdd(&sdeg[edge_at(ei, NE + e)], 1);
    __syncthreads();
    const int CHUNK = 10;  // 1024*10 >= NN
    int start = tid * CHUNK;
    int s = 0;
    for (int i = start; i < start + CHUNK && i < NN; i++) s += sdeg[i];
    ssum[tid] = s;
    __syncthreads();
    for (int off = 1; off < 1024; off <<= 1) {
        int v = (tid >= off) ? ssum[tid - off] : 0;
        __syncthreads();
        ssum[tid] += v;
        __syncthreads();
    }
    int run = ssum[tid] - s;
    for (int i = start; i < start + CHUNK && i < NN; i++) {
        g_rowptr[i] = run;
        run += sdeg[i];
    }
    if (tid == 1023) g_rowptr[NN] = ssum[1023];
    __syncthreads();
    for (int i = tid; i < NN; i += 1024) sdeg[i] = 0;   // now cursors
    __syncthreads();
    for (int e = tid; e < NE; e += 1024) {
        int srcn = edge_at(ei, e);
        int d    = edge_at(ei, NE + e);
        int p = atomicAdd(&sdeg[d], 1);
        g_col[g_rowptr[d] + p] = srcn;
    }
}

// ---------------- input transpose: x[b][n][c][t] -> X0[n][b*T+t][c] ----------------
__global__ void k_transpose(const float* __restrict__ x) {
    __shared__ float s[BT * 17];
    int n = blockIdx.x;
    for (int j = threadIdx.x; j < NB * CI * TT; j += blockDim.x) {
        int b = j / (CI * TT);
        int r = j % (CI * TT);
        int c = r / TT;
        int t = r % TT;
        s[(b * TT + t) * 17 + c] = x[((size_t)(b * NN + n)) * (CI * TT) + r];
    }
    __syncthreads();
    float* X0f = (float*)g_X0;
    for (int j = threadIdx.x; j < BT * CI; j += blockDim.x) {
        X0f[(size_t)n * (BT * CI) + j] = s[(j >> 4) * 17 + (j & 15)];
    }
}

// ================= pure gather: A[n][:] = X[n][:] + sum_src X[src][:] =================
template<bool L2PASS>
__global__ void __launch_bounds__(256) k_gather() {
    constexpr int NF4 = L2PASS ? (BT * CO / 4) : (BT * CI / 4);
    const float4* __restrict__ Xin = L2PASS ? g_Y1 : g_X0;
    float4* __restrict__ Aout = L2PASS ? g_A1 : g_A0;

    int n = blockIdx.x;
    int j = blockIdx.y * 256 + threadIdx.x;
    size_t base = (size_t)n * NF4 + j;
    float4 acc = Xin[base];
    float4 acc2 = make_float4(0.f, 0.f, 0.f, 0.f);
    int rs = g_rowptr[n], re = g_rowptr[n + 1];
    int e = rs;
    for (; e + 1 < re; e += 2) {
        float4 v0 = Xin[(size_t)g_col[e] * NF4 + j];
        float4 v1 = Xin[(size_t)g_col[e + 1] * NF4 + j];
        acc.x += v0.x;  acc.y += v0.y;  acc.z += v0.z;  acc.w += v0.w;
        acc2.x += v1.x; acc2.y += v1.y; acc2.z += v1.z; acc2.w += v1.w;
    }
    if (e < re) {
        float4 v = Xin[(size_t)g_col[e] * NF4 + j];
        acc.x += v.x; acc.y += v.y; acc.z += v.z; acc.w += v.w;
    }
    acc.x += acc2.x; acc.y += acc2.y; acc.z += acc2.z; acc.w += acc2.w;
    Aout[base] = acc;
}

// ================= dense MLP: 128 rows/block, 4 warps, constant-memory weights =================
// Warp w owns j/out range [8w, 8w+8); lane owns 4 rows (2 rowpairs).
// Weight reads are warp-uniform -> constant port (LDC), zero smem-crossbar bytes.
// Hidden processed in 32-wide chunks through s_h. No cross-warp reduction needed.
template<int KIN, int NHID, bool FINAL>
__global__ void __launch_bounds__(128) k_mlp(float* __restrict__ outT) {
    constexpr int KV  = KIN / 4;
    constexpr int NCH = NHID / 32;
    const float4* __restrict__ Ain = FINAL ? g_A1 : g_A0;

    __shared__ __align__(16) float s_act[KIN * 132];
    __shared__ __align__(16) float s_h[32 * 132];

    int tid = threadIdx.x;
    int w = tid >> 5, lid = tid & 31;
    size_t R0 = (size_t)blockIdx.x * 128;

    // ---- stage 128 rows (1 thread/row) -> k-major smem ----
    {
        float4 a[KV];
        size_t ro = (R0 + tid) * KV;
#pragma unroll
        for (int q = 0; q < KV; q++) a[q] = Ain[ro + q];
#pragma unroll
        for (int q = 0; q < KV; q++) {
            s_act[(4 * q + 0) * 132 + tid] = a[q].x;
            s_act[(4 * q + 1) * 132 + tid] = a[q].y;
            s_act[(4 * q + 2) * 132 + tid] = a[q].z;
            s_act[(4 * q + 3) * 132 + tid] = a[q].w;
        }
    }

    int jo = w * 8;     // warp's j-offset within chunk AND its out-offset
    int r4 = lid * 4;   // lane's first row

    // persistent GEMM2 accumulators: 8 outs x 2 rowpairs
    unsigned long long acc2[8][2];
#pragma unroll
    for (int o = 0; o < 8; o++) {
        float bv = FINAL ? c_b4[jo + o] : c_b2[jo + o];
        acc2[o][0] = acc2[o][1] = pk2(bv, bv);
    }
    __syncthreads();   // act staging visible

#pragma unroll
    for (int c = 0; c < NCH; c++) {
        // ---- GEMM1: h[jo..jo+8)[r4..r4+4) over k=0..KIN ----
        unsigned long long acc1[8][2];
#pragma unroll
        for (int o = 0; o < 8; o++) {
            float bv = FINAL ? c_b3[c * 32 + jo + o] : c_b1[c * 32 + jo + o];
            acc1[o][0] = acc1[o][1] = pk2(bv, bv);
        }
#pragma unroll 4
        for (int k = 0; k < KIN; k++) {
            ulonglong2 a = *(const ulonglong2*)&s_act[k * 132 + r4];
            float4 w0, w1;
            if (FINAL) {
                w0 = *(const float4*)&c_W3[k * NHID + c * 32 + jo];
                w1 = *(const float4*)&c_W3[k * NHID + c * 32 + jo + 4];
            } else {
                w0 = *(const float4*)&c_W1[k * NHID + c * 32 + jo];
                w1 = *(const float4*)&c_W1[k * NHID + c * 32 + jo + 4];
            }
            unsigned long long wd[8] = {pk2(w0.x, w0.x), pk2(w0.y, w0.y),
                                        pk2(w0.z, w0.z), pk2(w0.w, w0.w),
                                        pk2(w1.x, w1.x), pk2(w1.y, w1.y),
                                        pk2(w1.z, w1.z), pk2(w1.w, w1.w)};
#pragma unroll
            for (int o = 0; o < 8; o++) {
                acc1[o][0] = fma2(a.x, wd[o], acc1[o][0]);
                acc1[o][1] = fma2(a.y, wd[o], acc1[o][1]);
            }
        }
        // relu -> s_h[j][row]
#pragma unroll
        for (int o = 0; o < 8; o++) {
            float2 p0 = upk2(acc1[o][0]), p1 = upk2(acc1[o][1]);
            *(float4*)&s_h[(jo + o) * 132 + r4] =
                make_float4(fmaxf(p0.x, 0.f), fmaxf(p0.y, 0.f),
                            fmaxf(p1.x, 0.f), fmaxf(p1.y, 0.f));
        }
        __syncthreads();   // H chunk complete

        // ---- GEMM2: acc2 += h[k][r] * Wb[k][out], full chunk k per warp ----
#pragma unroll 4
        for (int kk = 0; kk < 32; kk++) {
            ulonglong2 a = *(const ulonglong2*)&s_h[kk * 132 + r4];
            float4 w0, w1;
            if (FINAL) {
                w0 = *(const float4*)&c_W4[(c * 32 + kk) * CO + jo];
                w1 = *(const float4*)&c_W4[(c * 32 + kk) * CO + jo + 4];
            } else {
                w0 = *(const float4*)&c_W2[(c * 32 + kk) * CO + jo];
                w1 = *(const float4*)&c_W2[(c * 32 + kk) * CO + jo + 4];
            }
            unsigned long long wd[8] = {pk2(w0.x, w0.x), pk2(w0.y, w0.y),
                                        pk2(w0.z, w0.z), pk2(w0.w, w0.w),
                                        pk2(w1.x, w1.x), pk2(w1.y, w1.y),
                                        pk2(w1.z, w1.z), pk2(w1.w, w1.w)};
#pragma unroll
            for (int o = 0; o < 8; o++) {
                acc2[o][0] = fma2(a.x, wd[o], acc2[o][0]);
                acc2[o][1] = fma2(a.y, wd[o], acc2[o][1]);
            }
        }
        __syncthreads();   // before next chunk overwrites s_h
    }

    // ---- epilogue ----
    if (!FINAL) {
        float4* Y = g_Y1;
#pragma unroll
        for (int s = 0; s < 4; s++) {
            int p = s >> 1;
            float f[8];
#pragma unroll
            for (int o = 0; o < 8; o++) {
                float2 t = upk2(acc2[o][p]);
                f[o] = (s & 1) ? t.y : t.x;
            }
            size_t bidx = (R0 + r4 + s) * 8 + w * 2;
            Y[bidx]     = make_float4(f[0], f[1], f[2], f[3]);
            Y[bidx + 1] = make_float4(f[4], f[5], f[6], f[7]);
        }
    } else {
#pragma unroll
        for (int s = 0; s < 4; s++) {
            int p = s >> 1;
            size_t rg = R0 + r4 + s;
            int n  = (int)(rg / BT);
            int rr = (int)(rg % BT);
            int b = rr / TT, t = rr % TT;
            size_t ob = ((size_t)(b * NN + n) * CO + jo) * TT + t;
#pragma unroll
            for (int o = 0; o < 8; o++) {
                float2 tv = upk2(acc2[o][p]);
                float v = (s & 1) ? tv.y : tv.x;
                outT[ob + (size_t)o * TT] = fmaxf(v, 0.f);
            }
        }
    }
}

// ---------------- launch ----------------
extern "C" void kernel_launch(void* const* d_in, const int* in_sizes, int n_in,
                              void* d_out, int out_size) {
    const float* x  = (const float*)d_in[0];
    const void*  ei = d_in[1];
    float* out = (float*)d_out;

    // weights -> constant memory (D2D async copies; graph-capturable)
    cudaMemcpyToSymbolAsync(c_W1, d_in[2], CI * 64 * 4,  0, cudaMemcpyDeviceToDevice);
    cudaMemcpyToSymbolAsync(c_b1, d_in[3], 64 * 4,       0, cudaMemcpyDeviceToDevice);
    cudaMemcpyToSymbolAsync(c_W2, d_in[4], 64 * CO * 4,  0, cudaMemcpyDeviceToDevice);
    cudaMemcpyToSymbolAsync(c_b2, d_in[5], CO * 4,       0, cudaMemcpyDeviceToDevice);
    cudaMemcpyToSymbolAsync(c_W3, d_in[6], CO * 128 * 4, 0, cudaMemcpyDeviceToDevice);
    cudaMemcpyToSymbolAsync(c_b3, d_in[7], 128 * 4,      0, cudaMemcpyDeviceToDevice);
    cudaMemcpyToSymbolAsync(c_W4, d_in[8], 128 * CO * 4, 0, cudaMemcpyDeviceToDevice);
    cudaMemcpyToSymbolAsync(c_b4, d_in[9], CO * 4,       0, cudaMemcpyDeviceToDevice);

    k_prepfill<<<1, 1024>>>(ei);
    k_transpose<<<NN, 256>>>(x);
    k_gather<false><<<dim3(NN, 3), 256>>>();
    k_mlp<CI, 64, false><<<NN * BT / 128, 128>>>(nullptr);
    k_gather<true><<<dim3(NN, 6), 256>>>();
    k_mlp<CO, 128, true><<<NN * BT / 128, 128>>>(out);
}

// round 12
// speedup vs baseline: 1.3465x; 1.3465x over previous
#include <cuda_runtime.h>

#define NB 8
#define NN 10000
#define CI 16
#define TT 24
#define CO 32
#define NE 160000
#define BT 192   // NB*TT

// ---------------- device scratch (float4-typed => 16B alignment) ----------------
__device__ float4 g_X0[(size_t)NN * BT * CI / 4];   // 123 MB layer-1 input (node-major)
__device__ float4 g_A0[(size_t)NN * BT * CI / 4];   // 123 MB layer-1 aggregated
__device__ float4 g_Y1[(size_t)NN * BT * CO / 4];   // 246 MB layer-1 output
__device__ float4 g_A1[(size_t)NN * BT * CO / 4];   // 246 MB layer-2 aggregated
__device__ int    g_rowptr[NN + 1];
__device__ int    g_col[NE];
__device__ int    g_is64;

// ---------------- packed f32x2 helpers ----------------
__device__ __forceinline__ unsigned long long fma2(unsigned long long a,
                                                   unsigned long long b,
                                                   unsigned long long c) {
    unsigned long long d;
    asm("fma.rn.f32x2 %0, %1, %2, %3;" : "=l"(d) : "l"(a), "l"(b), "l"(c));
    return d;
}
__device__ __forceinline__ unsigned long long pk2(float x, float y) {
    unsigned long long r;
    asm("mov.b64 %0, {%1, %2};" : "=l"(r) : "f"(x), "f"(y));
    return r;
}
__device__ __forceinline__ float2 upk2(unsigned long long a) {
    float2 r;
    asm("mov.b64 {%0, %1}, %2;" : "=f"(r.x), "=f"(r.y) : "l"(a));
    return r;
}

__device__ __forceinline__ int edge_at(const void* ei, int idx) {
    if (g_is64) return (int)((const long long*)ei)[idx];
    return ((const int*)ei)[idx];
}

// ---------------- CSR prep+fill: detect + histogram + scan + fill, ONE block ----------------
__global__ void __launch_bounds__(1024) k_prepfill(const void* ei) {
    __shared__ int sdeg[NN];    // degree, then reused as fill cursor
    __shared__ int ssum[1024];
    int tid = threadIdx.x;
    if (tid == 0) {
        const long long* p = (const long long*)ei;
        int ok64 = 1;
        for (int q = 0; q < 64; q++) {
            long long v = p[q];
            if (v < 0 || v >= NN) { ok64 = 0; break; }
        }
        g_is64 = ok64;
    }
    __syncthreads();
    for (int i = tid; i < NN; i += 1024) sdeg[i] = 0;
    __syncthreads();
    for (int e = tid; e < NE; e += 1024) atomicAdd(&sdeg[edge_at(ei, NE + e)], 1);
    __syncthreads();
    const int CHUNK = 10;
    int start = tid * CHUNK;
    int s = 0;
    for (int i = start; i < start + CHUNK && i < NN; i++) s += sdeg[i];
    ssum[tid] = s;
    __syncthreads();
    for (int off = 1; off < 1024; off <<= 1) {
        int v = (tid >= off) ? ssum[tid - off] : 0;
        __syncthreads();
        ssum[tid] += v;
        __syncthreads();
    }
    int run = ssum[tid] - s;
    for (int i = start; i < start + CHUNK && i < NN; i++) {
        g_rowptr[i] = run;
        run += sdeg[i];
    }
    if (tid == 1023) g_rowptr[NN] = ssum[1023];
    __syncthreads();
    for (int i = tid; i < NN; i += 1024) sdeg[i] = 0;   // now cursors
    __syncthreads();
    for (int e = tid; e < NE; e += 1024) {
        int srcn = edge_at(ei, e);
        int d    = edge_at(ei, NE + e);
        int p = atomicAdd(&sdeg[d], 1);
        g_col[g_rowptr[d] + p] = srcn;
    }
}

// ---------------- input transpose: x[b][n][c][t] -> X0[n][b*T+t][c] ----------------
__global__ void k_transpose(const float* __restrict__ x) {
    __shared__ float s[BT * 17];
    int n = blockIdx.x;
    for (int j = threadIdx.x; j < NB * CI * TT; j += blockDim.x) {
        int b = j / (CI * TT);
        int r = j % (CI * TT);
        int c = r / TT;
        int t = r % TT;
        s[(b * TT + t) * 17 + c] = x[((size_t)(b * NN + n)) * (CI * TT) + r];
    }
    __syncthreads();
    float* X0f = (float*)g_X0;
    for (int j = threadIdx.x; j < BT * CI; j += blockDim.x) {
        X0f[(size_t)n * (BT * CI) + j] = s[(j >> 4) * 17 + (j & 15)];
    }
}

// ================= pure gather: A[n][:] = X[n][:] + sum_src X[src][:] =================
template<bool L2PASS>
__global__ void __launch_bounds__(256) k_gather() {
    constexpr int NF4 = L2PASS ? (BT * CO / 4) : (BT * CI / 4);
    const float4* __restrict__ Xin = L2PASS ? g_Y1 : g_X0;
    float4* __restrict__ Aout = L2PASS ? g_A1 : g_A0;

    int n = blockIdx.x;
    int j = blockIdx.y * 256 + threadIdx.x;
    size_t base = (size_t)n * NF4 + j;
    float4 acc = Xin[base];
    float4 acc2 = make_float4(0.f, 0.f, 0.f, 0.f);
    int rs = g_rowptr[n], re = g_rowptr[n + 1];
    int e = rs;
    for (; e + 1 < re; e += 2) {
        float4 v0 = Xin[(size_t)g_col[e] * NF4 + j];
        float4 v1 = Xin[(size_t)g_col[e + 1] * NF4 + j];
        acc.x += v0.x;  acc.y += v0.y;  acc.z += v0.z;  acc.w += v0.w;
        acc2.x += v1.x; acc2.y += v1.y; acc2.z += v1.z; acc2.w += v1.w;
    }
    if (e < re) {
        float4 v = Xin[(size_t)g_col[e] * NF4 + j];
        acc.x += v.x; acc.y += v.y; acc.z += v.z; acc.w += v.w;
    }
    acc.x += acc2.x; acc.y += acc2.y; acc.z += acc2.z; acc.w += acc2.w;
    Aout[base] = acc;
}

// ================= dense MLP: 128 rows/block, 4 warps, smem weights w/ BROADCAST reads =================
// Warp w owns out/j range [8w, 8w+8); lane owns 4 rows. Weight LDS addresses are
// warp-uniform -> broadcast (N=1, no crossbar cost). Hidden in 32-wide chunks.
template<int KIN, int NHID, bool FINAL>
__global__ void __launch_bounds__(128) k_mlp(
    const float* __restrict__ Wa, const float* __restrict__ ba,   // [KIN][NHID], [NHID]
    const float* __restrict__ Wb, const float* __restrict__ bb,   // [NHID][32], [32]
    float* __restrict__ outT)
{
    constexpr int KV  = KIN / 4;
    constexpr int NCH = NHID / 32;
    const float4* __restrict__ Ain = FINAL ? g_A1 : g_A0;

    __shared__ __align__(16) float s_act[KIN * 132];
    __shared__ __align__(16) float s_h[32 * 132];
    __shared__ __align__(16) float s_wa[KIN * 32];
    __shared__ __align__(16) float s_wb[32 * 32];
    __shared__ float s_ba[32];

    int tid = threadIdx.x;
    int w = tid >> 5, lid = tid & 31;
    size_t R0 = (size_t)blockIdx.x * 128;

    // ---- stage 128 rows (1 thread/row) -> k-major smem ----
    {
        float4 a[KV];
        size_t ro = (R0 + tid) * KV;
#pragma unroll
        for (int q = 0; q < KV; q++) a[q] = Ain[ro + q];
#pragma unroll
        for (int q = 0; q < KV; q++) {
            s_act[(4 * q + 0) * 132 + tid] = a[q].x;
            s_act[(4 * q + 1) * 132 + tid] = a[q].y;
            s_act[(4 * q + 2) * 132 + tid] = a[q].z;
            s_act[(4 * q + 3) * 132 + tid] = a[q].w;
        }
    }

    int jo = w * 8;     // warp's j-offset within chunk AND its out-offset
    int r4 = lid * 4;   // lane's first row

    // persistent GEMM2 accumulators: 8 outs x 2 rowpairs
    unsigned long long acc2[8][2];
#pragma unroll
    for (int o = 0; o < 8; o++) {
        float bv = bb[jo + o];
        acc2[o][0] = acc2[o][1] = pk2(bv, bv);
    }

    for (int c = 0; c < NCH; c++) {
        __syncthreads();   // prev chunk's weight reads done (and act staged on c=0)
        // ---- stage chunk weights ----
        {
            const float4* Wav = (const float4*)Wa;   // [KIN][NHID/4]
            for (int i = tid; i < KIN * 8; i += 128) {
                int k = i >> 3, jv = i & 7;
                ((float4*)s_wa)[k * 8 + jv] = Wav[k * (NHID / 4) + c * 8 + jv];
            }
            const float4* Wbv = (const float4*)Wb;   // [NHID][8]
            if (tid < 64) {
                ((float4*)s_wb)[tid * 4 + 0] = Wbv[(c * 32 + (tid >> 1)) * 8 + (tid & 1) * 4 + 0];
                ((float4*)s_wb)[tid * 4 + 1] = Wbv[(c * 32 + (tid >> 1)) * 8 + (tid & 1) * 4 + 1];
                ((float4*)s_wb)[tid * 4 + 2] = Wbv[(c * 32 + (tid >> 1)) * 8 + (tid & 1) * 4 + 2];
                ((float4*)s_wb)[tid * 4 + 3] = Wbv[(c * 32 + (tid >> 1)) * 8 + (tid & 1) * 4 + 3];
            }
            if (tid < 32) s_ba[tid] = ba[c * 32 + tid];
        }
        __syncthreads();   // weights visible

        // ---- GEMM1: h[jo..jo+8)[r4..r4+4) over k=0..KIN ----
        unsigned long long acc1[8][2];
#pragma unroll
        for (int o = 0; o < 8; o++) {
            float bv = s_ba[jo + o];
            acc1[o][0] = acc1[o][1] = pk2(bv, bv);
        }
#pragma unroll 4
        for (int k = 0; k < KIN; k++) {
            ulonglong2 a = *(const ulonglong2*)&s_act[k * 132 + r4];
            float4 w0 = *(const float4*)&s_wa[k * 32 + jo];        // broadcast
            float4 w1 = *(const float4*)&s_wa[k * 32 + jo + 4];    // broadcast
            unsigned long long wd[8] = {pk2(w0.x, w0.x), pk2(w0.y, w0.y),
                                        pk2(w0.z, w0.z), pk2(w0.w, w0.w),
                                        pk2(w1.x, w1.x), pk2(w1.y, w1.y),
                                        pk2(w1.z, w1.z), pk2(w1.w, w1.w)};
#pragma unroll
            for (int o = 0; o < 8; o++) {
                acc1[o][0] = fma2(a.x, wd[o], acc1[o][0]);
                acc1[o][1] = fma2(a.y, wd[o], acc1[o][1]);
            }
        }
        // relu -> s_h[j][row]
#pragma unroll
        for (int o = 0; o < 8; o++) {
            float2 p0 = upk2(acc1[o][0]), p1 = upk2(acc1[o][1]);
            *(float4*)&s_h[(jo + o) * 132 + r4] =
                make_float4(fmaxf(p0.x, 0.f), fmaxf(p0.y, 0.f),
                            fmaxf(p1.x, 0.f), fmaxf(p1.y, 0.f));
        }
        __syncthreads();   // H chunk complete

        // ---- GEMM2: acc2 += h[k][r] * Wb[k][out] over full chunk ----
#pragma unroll 4
        for (int kk = 0; kk < 32; kk++) {
            ulonglong2 a = *(const ulonglong2*)&s_h[kk * 132 + r4];
            float4 w0 = *(const float4*)&s_wb[kk * 32 + jo];       // broadcast
            float4 w1 = *(const float4*)&s_wb[kk * 32 + jo + 4];   // broadcast
            unsigned long long wd[8] = {pk2(w0.x, w0.x), pk2(w0.y, w0.y),
                                        pk2(w0.z, w0.z), pk2(w0.w, w0.w),
                                        pk2(w1.x, w1.x), pk2(w1.y, w1.y),
                                        pk2(w1.z, w1.z), pk2(w1.w, w1.w)};
#pragma unroll
            for (int o = 0; o < 8; o++) {
                acc2[o][0] = fma2(a.x, wd[o], acc2[o][0]);
                acc2[o][1] = fma2(a.y, wd[o], acc2[o][1]);
            }
        }
    }

    // ---- epilogue ----
    if (!FINAL) {
        float4* Y = g_Y1;
#pragma unroll
        for (int s = 0; s < 4; s++) {
            int p = s >> 1;
            float f[8];
#pragma unroll
            for (int o = 0; o < 8; o++) {
                float2 t = upk2(acc2[o][p]);
                f[o] = (s & 1) ? t.y : t.x;
            }
            size_t bidx = (R0 + r4 + s) * 8 + w * 2;
            Y[bidx]     = make_float4(f[0], f[1], f[2], f[3]);
            Y[bidx + 1] = make_float4(f[4], f[5], f[6], f[7]);
        }
    } else {
#pragma unroll
        for (int s = 0; s < 4; s++) {
            int p = s >> 1;
            size_t rg = R0 + r4 + s;
            int n  = (int)(rg / BT);
            int rr = (int)(rg % BT);
            int b = rr / TT, t = rr % TT;
            size_t ob = ((size_t)(b * NN + n) * CO + jo) * TT + t;
#pragma unroll
            for (int o = 0; o < 8; o++) {
                float2 tv = upk2(acc2[o][p]);
                float v = (s & 1) ? tv.y : tv.x;
                outT[ob + (size_t)o * TT] = fmaxf(v, 0.f);
            }
        }
    }
}

// ---------------- launch ----------------
extern "C" void kernel_launch(void* const* d_in, const int* in_sizes, int n_in,
                              void* d_out, int out_size) {
    const float* x  = (const float*)d_in[0];
    const void*  ei = d_in[1];
    const float* W1 = (const float*)d_in[2];
    const float* b1 = (const float*)d_in[3];
    const float* W2 = (const float*)d_in[4];
    const float* b2 = (const float*)d_in[5];
    const float* W3 = (const float*)d_in[6];
    const float* b3 = (const float*)d_in[7];
    const float* W4 = (const float*)d_in[8];
    const float* b4 = (const float*)d_in[9];
    float* out = (float*)d_out;

    k_prepfill<<<1, 1024>>>(ei);
    k_transpose<<<NN, 256>>>(x);
    k_gather<false><<<dim3(NN, 3), 256>>>();
    k_mlp<CI, 64, false><<<NN * BT / 128, 128>>>(W1, b1, W2, b2, nullptr);
    k_gather<true><<<dim3(NN, 6), 256>>>();
    k_mlp<CO, 128, true><<<NN * BT / 128, 128>>>(W3, b3, W4, b4, out);
}

// round 13
// speedup vs baseline: 1.3657x; 1.0143x over previous
#include <cuda_runtime.h>

#define NB 8
#define NN 10000
#define CI 16
#define TT 24
#define CO 32
#define NE 160000
#define BT 192   // NB*TT

// ---------------- device scratch (float4-typed => 16B alignment) ----------------
__device__ float4 g_X0[(size_t)NN * BT * CI / 4];   // 123 MB layer-1 input (node-major)
__device__ float4 g_A0[(size_t)NN * BT * CI / 4];   // 123 MB layer-1 aggregated
__device__ float4 g_Y1[(size_t)NN * BT * CO / 4];   // 246 MB layer-1 output
__device__ float4 g_A1[(size_t)NN * BT * CO / 4];   // 246 MB layer-2 aggregated
__device__ int    g_rowptr[NN + 1];
__device__ int    g_col[NE];
__device__ int    g_is64;

// ---------------- packed f32x2 helpers ----------------
__device__ __forceinline__ unsigned long long fma2(unsigned long long a,
                                                   unsigned long long b,
                                                   unsigned long long c) {
    unsigned long long d;
    asm("fma.rn.f32x2 %0, %1, %2, %3;" : "=l"(d) : "l"(a), "l"(b), "l"(c));
    return d;
}
__device__ __forceinline__ unsigned long long pk2(float x, float y) {
    unsigned long long r;
    asm("mov.b64 %0, {%1, %2};" : "=l"(r) : "f"(x), "f"(y));
    return r;
}
__device__ __forceinline__ float2 upk2(unsigned long long a) {
    float2 r;
    asm("mov.b64 {%0, %1}, %2;" : "=f"(r.x), "=f"(r.y) : "l"(a));
    return r;
}

__device__ __forceinline__ int edge_at(const void* ei, int idx) {
    if (g_is64) return (int)((const long long*)ei)[idx];
    return ((const int*)ei)[idx];
}

// ---------------- CSR prep+fill: detect + histogram + scan + fill, ONE block ----------------
__global__ void __launch_bounds__(1024) k_prepfill(const void* ei) {
    __shared__ int sdeg[NN];
    __shared__ int ssum[1024];
    int tid = threadIdx.x;
    if (tid == 0) {
        const long long* p = (const long long*)ei;
        int ok64 = 1;
        for (int q = 0; q < 64; q++) {
            long long v = p[q];
            if (v < 0 || v >= NN) { ok64 = 0; break; }
        }
        g_is64 = ok64;
    }
    __syncthreads();
    for (int i = tid; i < NN; i += 1024) sdeg[i] = 0;
    __syncthreads();
    for (int e = tid; e < NE; e += 1024) atomicAdd(&sdeg[edge_at(ei, NE + e)], 1);
    __syncthreads();
    const int CHUNK = 10;
    int start = tid * CHUNK;
    int s = 0;
    for (int i = start; i < start + CHUNK && i < NN; i++) s += sdeg[i];
    ssum[tid] = s;
    __syncthreads();
    for (int off = 1; off < 1024; off <<= 1) {
        int v = (tid >= off) ? ssum[tid - off] : 0;
        __syncthreads();
        ssum[tid] += v;
        __syncthreads();
    }
    int run = ssum[tid] - s;
    for (int i = start; i < start + CHUNK && i < NN; i++) {
        g_rowptr[i] = run;
        run += sdeg[i];
    }
    if (tid == 1023) g_rowptr[NN] = ssum[1023];
    __syncthreads();
    for (int i = tid; i < NN; i += 1024) sdeg[i] = 0;   // now cursors
    __syncthreads();
    for (int e = tid; e < NE; e += 1024) {
        int srcn = edge_at(ei, e);
        int d    = edge_at(ei, NE + e);
        int p = atomicAdd(&sdeg[d], 1);
        g_col[g_rowptr[d] + p] = srcn;
    }
}

// ---------------- input transpose: x[b][n][c][t] -> X0[n][b*T+t][c] ----------------
__global__ void k_transpose(const float* __restrict__ x) {
    __shared__ float s[BT * 17];
    int n = blockIdx.x;
    for (int j = threadIdx.x; j < NB * CI * TT; j += blockDim.x) {
        int b = j / (CI * TT);
        int r = j % (CI * TT);
        int c = r / TT;
        int t = r % TT;
        s[(b * TT + t) * 17 + c] = x[((size_t)(b * NN + n)) * (CI * TT) + r];
    }
    __syncthreads();
    float* X0f = (float*)g_X0;
    for (int j = threadIdx.x; j < BT * CI; j += blockDim.x) {
        X0f[(size_t)n * (BT * CI) + j] = s[(j >> 4) * 17 + (j & 15)];
    }
}

// ================= pure gather: A[n][:] = X[n][:] + sum_src X[src][:] =================
template<bool L2PASS>
__global__ void __launch_bounds__(256) k_gather() {
    constexpr int NF4 = L2PASS ? (BT * CO / 4) : (BT * CI / 4);
    const float4* __restrict__ Xin = L2PASS ? g_Y1 : g_X0;
    float4* __restrict__ Aout = L2PASS ? g_A1 : g_A0;

    int n = blockIdx.x;
    int j = blockIdx.y * 256 + threadIdx.x;
    size_t base = (size_t)n * NF4 + j;
    float4 acc = Xin[base];
    float4 acc2 = make_float4(0.f, 0.f, 0.f, 0.f);
    int rs = g_rowptr[n], re = g_rowptr[n + 1];
    int e = rs;
    for (; e + 1 < re; e += 2) {
        float4 v0 = Xin[(size_t)g_col[e] * NF4 + j];
        float4 v1 = Xin[(size_t)g_col[e + 1] * NF4 + j];
        acc.x += v0.x;  acc.y += v0.y;  acc.z += v0.z;  acc.w += v0.w;
        acc2.x += v1.x; acc2.y += v1.y; acc2.z += v1.z; acc2.w += v1.w;
    }
    if (e < re) {
        float4 v = Xin[(size_t)g_col[e] * NF4 + j];
        acc.x += v.x; acc.y += v.y; acc.z += v.z; acc.w += v.w;
    }
    acc.x += acc2.x; acc.y += acc2.y; acc.z += acc2.z; acc.w += acc2.w;
    Aout[base] = acc;
}

// ================= dense MLP: 256 rows/block, 128 thr, J=8 x P=4 balanced tiles =================
// Lane owns 8 rows: {r4..r4+4} and {128+r4..}. Per k: 2 act LDS.128 (BW-bound, conflict-free)
// + 2 broadcast weight LDS.128 vs 32 fma2  ==>  crossbar == fma at the 4-cyc instr floor.
// Dynamic smem (s_act KIN*256 + s_h 32*256 + chunk weights).
template<int KIN, int NHID, bool FINAL>
__global__ void __launch_bounds__(128) k_mlp(
    const float* __restrict__ Wa, const float* __restrict__ ba,   // [KIN][NHID], [NHID]
    const float* __restrict__ Wb, const float* __restrict__ bb,   // [NHID][32], [32]
    float* __restrict__ outT)
{
    constexpr int KV  = KIN / 4;
    constexpr int NCH = NHID / 32;
    const float4* __restrict__ Ain = FINAL ? g_A1 : g_A0;

    extern __shared__ __align__(16) float sm[];
    float* s_act = sm;                       // KIN*256
    float* s_h   = s_act + KIN * 256;        // 32*256
    float* s_wa  = s_h + 32 * 256;           // KIN*32
    float* s_wb  = s_wa + KIN * 32;          // 32*32
    float* s_ba  = s_wb + 32 * 32;           // 32

    int tid = threadIdx.x;
    int w = tid >> 5, lid = tid & 31;
    size_t R0 = (size_t)blockIdx.x * 256;

    // ---- stage 256 rows (2 rows/thread) -> k-major smem ----
#pragma unroll
    for (int g = 0; g < 2; g++) {
        int row = tid + g * 128;
        float4 a[KV];
        size_t ro = (R0 + row) * KV;
#pragma unroll
        for (int q = 0; q < KV; q++) a[q] = Ain[ro + q];
#pragma unroll
        for (int q = 0; q < KV; q++) {
            s_act[(4 * q + 0) * 256 + row] = a[q].x;
            s_act[(4 * q + 1) * 256 + row] = a[q].y;
            s_act[(4 * q + 2) * 256 + row] = a[q].z;
            s_act[(4 * q + 3) * 256 + row] = a[q].w;
        }
    }

    int jo = w * 8;     // warp's j-offset within chunk AND out-offset
    int r4 = lid * 4;   // lane's group-A row base (group B = +128)

    // persistent GEMM2 accumulators: 8 outs x 4 rowpairs (p0,p1 = group A; p2,p3 = group B)
    unsigned long long acc2[8][4];
#pragma unroll
    for (int o = 0; o < 8; o++) {
        float bv = bb[jo + o];
        unsigned long long bp = pk2(bv, bv);
#pragma unroll
        for (int p = 0; p < 4; p++) acc2[o][p] = bp;
    }

    for (int c = 0; c < NCH; c++) {
        __syncthreads();   // prev chunk reads done (and act staged on c=0)
        // ---- stage chunk weights ----
        {
            const float4* Wav = (const float4*)Wa;   // [KIN][NHID/4]
            for (int i = tid; i < KIN * 8; i += 128) {
                int k = i >> 3, jv = i & 7;
                ((float4*)s_wa)[k * 8 + jv] = Wav[k * (NHID / 4) + c * 8 + jv];
            }
            const float4* Wbv = (const float4*)Wb;   // [NHID][8]
            for (int i = tid; i < 256; i += 128)
                ((float4*)s_wb)[i] = Wbv[c * 256 + i];
            if (tid < 32) s_ba[tid] = ba[c * 32 + tid];
        }
        __syncthreads();   // weights visible

        // ---- GEMM1: h[jo..jo+8)[lane's 8 rows] over k=0..KIN ----
        unsigned long long acc1[8][4];
#pragma unroll
        for (int o = 0; o < 8; o++) {
            float bv = s_ba[jo + o];
            unsigned long long bp = pk2(bv, bv);
#pragma unroll
            for (int p = 0; p < 4; p++) acc1[o][p] = bp;
        }
#pragma unroll 4
        for (int k = 0; k < KIN; k++) {
            ulonglong2 aA = *(const ulonglong2*)&s_act[k * 256 + r4];
            ulonglong2 aB = *(const ulonglong2*)&s_act[k * 256 + 128 + r4];
            float4 w0 = *(const float4*)&s_wa[k * 32 + jo];        // broadcast
            float4 w1 = *(const float4*)&s_wa[k * 32 + jo + 4];    // broadcast
            unsigned long long wd[8] = {pk2(w0.x, w0.x), pk2(w0.y, w0.y),
                                        pk2(w0.z, w0.z), pk2(w0.w, w0.w),
                                        pk2(w1.x, w1.x), pk2(w1.y, w1.y),
                                        pk2(w1.z, w1.z), pk2(w1.w, w1.w)};
#pragma unroll
            for (int o = 0; o < 8; o++) {
                acc1[o][0] = fma2(aA.x, wd[o], acc1[o][0]);
                acc1[o][1] = fma2(aA.y, wd[o], acc1[o][1]);
                acc1[o][2] = fma2(aB.x, wd[o], acc1[o][2]);
                acc1[o][3] = fma2(aB.y, wd[o], acc1[o][3]);
            }
        }
        // relu -> s_h[j][row], both row groups
#pragma unroll
        for (int o = 0; o < 8; o++) {
            float2 p0 = upk2(acc1[o][0]), p1 = upk2(acc1[o][1]);
            float2 p2 = upk2(acc1[o][2]), p3 = upk2(acc1[o][3]);
            *(float4*)&s_h[(jo + o) * 256 + r4] =
                make_float4(fmaxf(p0.x, 0.f), fmaxf(p0.y, 0.f),
                            fmaxf(p1.x, 0.f), fmaxf(p1.y, 0.f));
            *(float4*)&s_h[(jo + o) * 256 + 128 + r4] =
                make_float4(fmaxf(p2.x, 0.f), fmaxf(p2.y, 0.f),
                            fmaxf(p3.x, 0.f), fmaxf(p3.y, 0.f));
        }
        __syncthreads();   // H chunk complete

        // ---- GEMM2: acc2 += h[k][rows] * Wb[k][out] over full chunk ----
#pragma unroll 4
        for (int kk = 0; kk < 32; kk++) {
            ulonglong2 aA = *(const ulonglong2*)&s_h[kk * 256 + r4];
            ulonglong2 aB = *(const ulonglong2*)&s_h[kk * 256 + 128 + r4];
            float4 w0 = *(const float4*)&s_wb[kk * 32 + jo];       // broadcast
            float4 w1 = *(const float4*)&s_wb[kk * 32 + jo + 4];   // broadcast
            unsigned long long wd[8] = {pk2(w0.x, w0.x), pk2(w0.y, w0.y),
                                        pk2(w0.z, w0.z), pk2(w0.w, w0.w),
                                        pk2(w1.x, w1.x), pk2(w1.y, w1.y),
                                        pk2(w1.z, w1.z), pk2(w1.w, w1.w)};
#pragma unroll
            for (int o = 0; o < 8; o++) {
                acc2[o][0] = fma2(aA.x, wd[o], acc2[o][0]);
                acc2[o][1] = fma2(aA.y, wd[o], acc2[o][1]);
                acc2[o][2] = fma2(aB.x, wd[o], acc2[o][2]);
                acc2[o][3] = fma2(aB.y, wd[o], acc2[o][3]);
            }
        }
    }

    // ---- epilogue: lane's 8 rows = {r4+q} U {128+r4+q} ----
    if (!FINAL) {
        float4* Y = g_Y1;
#pragma unroll
        for (int g = 0; g < 2; g++) {
#pragma unroll
            for (int s = 0; s < 4; s++) {
                int p = g * 2 + (s >> 1);
                float f[8];
#pragma unroll
                for (int o = 0; o < 8; o++) {
                    float2 t = upk2(acc2[o][p]);
                    f[o] = (s & 1) ? t.y : t.x;
                }
                size_t bidx = (R0 + g * 128 + r4 + s) * 8 + w * 2;
                Y[bidx]     = make_float4(f[0], f[1], f[2], f[3]);
                Y[bidx + 1] = make_float4(f[4], f[5], f[6], f[7]);
            }
        }
    } else {
#pragma unroll
        for (int g = 0; g < 2; g++) {
#pragma unroll
            for (int s = 0; s < 4; s++) {
                int p = g * 2 + (s >> 1);
                size_t rg = R0 + g * 128 + r4 + s;
                int n  = (int)(rg / BT);
                int rr = (int)(rg % BT);
                int b = rr / TT, t = rr % TT;
                size_t ob = ((size_t)(b * NN + n) * CO + jo) * TT + t;
#pragma unroll
                for (int o = 0; o < 8; o++) {
                    float2 tv = upk2(acc2[o][p]);
                    float v = (s & 1) ? tv.y : tv.x;
                    outT[ob + (size_t)o * TT] = fmaxf(v, 0.f);
                }
            }
        }
    }
}

// ---------------- launch ----------------
extern "C" void kernel_launch(void* const* d_in, const int* in_sizes, int n_in,
                              void* d_out, int out_size) {
    const float* x  = (const float*)d_in[0];
    const void*  ei = d_in[1];
    const float* W1 = (const float*)d_in[2];
    const float* b1 = (const float*)d_in[3];
    const float* W2 = (const float*)d_in[4];
    const float* b2 = (const float*)d_in[5];
    const float* W3 = (const float*)d_in[6];
    const float* b3 = (const float*)d_in[7];
    const float* W4 = (const float*)d_in[8];
    const float* b4 = (const float*)d_in[9];
    float* out = (float*)d_out;

    const int SMEM1 = (CI * 256 + 32 * 256 + CI * 32 + 32 * 32 + 32) * 4;  // 55,424 B
    const int SMEM2 = (CO * 256 + 32 * 256 + CO * 32 + 32 * 32 + 32) * 4;  // 73,856 B
    cudaFuncSetAttribute(k_mlp<CI, 64, false>,
                         cudaFuncAttributeMaxDynamicSharedMemorySize, SMEM1);
    cudaFuncSetAttribute(k_mlp<CO, 128, true>,
                         cudaFuncAttributeMaxDynamicSharedMemorySize, SMEM2);

    k_prepfill<<<1, 1024>>>(ei);
    k_transpose<<<NN, 256>>>(x);
    k_gather<false><<<dim3(NN, 3), 256>>>();
    k_mlp<CI, 64, false><<<NN * BT / 256, 128, SMEM1>>>(W1, b1, W2, b2, nullptr);
    k_gather<true><<<dim3(NN, 6), 256>>>();
    k_mlp<CO, 128, true><<<NN * BT / 256, 128, SMEM2>>>(W3, b3, W4, b4, out);
}

// round 14
// speedup vs baseline: 1.4085x; 1.0313x over previous
#include <cuda_runtime.h>

#define NB 8
#define NN 10000
#define CI 16
#define TT 24
#define CO 32
#define NE 160000
#define BT 192   // NB*TT

// ---------------- device scratch (float4-typed => 16B alignment) ----------------
__device__ float4 g_X0[(size_t)NN * BT * CI / 4];   // 123 MB layer-1 input (node-major)
__device__ float4 g_A0[(size_t)NN * BT * CI / 4];   // 123 MB layer-1 aggregated
__device__ float4 g_Y1[(size_t)NN * BT * CO / 4];   // 246 MB layer-1 output
__device__ float4 g_A1[(size_t)NN * BT * CO / 4];   // 246 MB layer-2 aggregated
__device__ int    g_rowptr[NN + 1];
__device__ int    g_col[NE];
__device__ int    g_is64;

// ---------------- packed f32x2 helpers ----------------
__device__ __forceinline__ unsigned long long fma2(unsigned long long a,
                                                   unsigned long long b,
                                                   unsigned long long c) {
    unsigned long long d;
    asm("fma.rn.f32x2 %0, %1, %2, %3;" : "=l"(d) : "l"(a), "l"(b), "l"(c));
    return d;
}
__device__ __forceinline__ unsigned long long pk2(float x, float y) {
    unsigned long long r;
    asm("mov.b64 %0, {%1, %2};" : "=l"(r) : "f"(x), "f"(y));
    return r;
}
__device__ __forceinline__ float2 upk2(unsigned long long a) {
    float2 r;
    asm("mov.b64 {%0, %1}, %2;" : "=f"(r.x), "=f"(r.y) : "l"(a));
    return r;
}

__device__ __forceinline__ int edge_at(const void* ei, int idx) {
    if (g_is64) return (int)((const long long*)ei)[idx];
    return ((const int*)ei)[idx];
}

// ---------------- CSR prep+fill: detect + histogram + scan + fill, ONE block ----------------
__global__ void __launch_bounds__(1024) k_prepfill(const void* ei) {
    __shared__ int sdeg[NN];
    __shared__ int ssum[1024];
    int tid = threadIdx.x;
    if (tid == 0) {
        const long long* p = (const long long*)ei;
        int ok64 = 1;
        for (int q = 0; q < 64; q++) {
            long long v = p[q];
            if (v < 0 || v >= NN) { ok64 = 0; break; }
        }
        g_is64 = ok64;
    }
    __syncthreads();
    for (int i = tid; i < NN; i += 1024) sdeg[i] = 0;
    __syncthreads();
    for (int e = tid; e < NE; e += 1024) atomicAdd(&sdeg[edge_at(ei, NE + e)], 1);
    __syncthreads();
    const int CHUNK = 10;
    int start = tid * CHUNK;
    int s = 0;
    for (int i = start; i < start + CHUNK && i < NN; i++) s += sdeg[i];
    ssum[tid] = s;
    __syncthreads();
    for (int off = 1; off < 1024; off <<= 1) {
        int v = (tid >= off) ? ssum[tid - off] : 0;
        __syncthreads();
        ssum[tid] += v;
        __syncthreads();
    }
    int run = ssum[tid] - s;
    for (int i = start; i < start + CHUNK && i < NN; i++) {
        g_rowptr[i] = run;
        run += sdeg[i];
    }
    if (tid == 1023) g_rowptr[NN] = ssum[1023];
    __syncthreads();
    for (int i = tid; i < NN; i += 1024) sdeg[i] = 0;   // now cursors
    __syncthreads();
    for (int e = tid; e < NE; e += 1024) {
        int srcn = edge_at(ei, e);
        int d    = edge_at(ei, NE + e);
        int p = atomicAdd(&sdeg[d], 1);
        g_col[g_rowptr[d] + p] = srcn;
    }
}

// ---------------- input transpose: x[b][n][c][t] -> X0[n][b*T+t][c] ----------------
__global__ void k_transpose(const float* __restrict__ x) {
    __shared__ float s[BT * 17];
    int n = blockIdx.x;
    for (int j = threadIdx.x; j < NB * CI * TT; j += blockDim.x) {
        int b = j / (CI * TT);
        int r = j % (CI * TT);
        int c = r / TT;
        int t = r % TT;
        s[(b * TT + t) * 17 + c] = x[((size_t)(b * NN + n)) * (CI * TT) + r];
    }
    __syncthreads();
    float* X0f = (float*)g_X0;
    for (int j = threadIdx.x; j < BT * CI; j += blockDim.x) {
        X0f[(size_t)n * (BT * CI) + j] = s[(j >> 4) * 17 + (j & 15)];
    }
}

// ================= pure gather: A[n][jbase..] = X[n][..] + sum_src X[src][..] =================
template<bool L2PASS>
__global__ void __launch_bounds__(256) k_gather(int jbase) {
    constexpr int NF4 = L2PASS ? (BT * CO / 4) : (BT * CI / 4);
    const float4* __restrict__ Xin = L2PASS ? g_Y1 : g_X0;
    float4* __restrict__ Aout = L2PASS ? g_A1 : g_A0;

    int n = blockIdx.x;
    int j = jbase + blockIdx.y * 256 + threadIdx.x;
    size_t base = (size_t)n * NF4 + j;
    float4 acc = Xin[base];
    float4 acc2 = make_float4(0.f, 0.f, 0.f, 0.f);
    int rs = g_rowptr[n], re = g_rowptr[n + 1];
    int e = rs;
    for (; e + 1 < re; e += 2) {
        float4 v0 = Xin[(size_t)g_col[e] * NF4 + j];
        float4 v1 = Xin[(size_t)g_col[e + 1] * NF4 + j];
        acc.x += v0.x;  acc.y += v0.y;  acc.z += v0.z;  acc.w += v0.w;
        acc2.x += v1.x; acc2.y += v1.y; acc2.z += v1.z; acc2.w += v1.w;
    }
    if (e < re) {
        float4 v = Xin[(size_t)g_col[e] * NF4 + j];
        acc.x += v.x; acc.y += v.y; acc.z += v.z; acc.w += v.w;
    }
    acc.x += acc2.x; acc.y += acc2.y; acc.z += acc2.z; acc.w += acc2.w;
    Aout[base] = acc;
}

// ================= dense MLP over ONE 64-row slab: block = 4 nodes x 64 slab rows =================
// J=8 x P=4 balanced f32x2 tiles (round-13 inner loops unchanged).
template<int KIN, int NHID, bool FINAL>
__global__ void __launch_bounds__(128) k_mlp(
    int slab,
    const float* __restrict__ Wa, const float* __restrict__ ba,   // [KIN][NHID], [NHID]
    const float* __restrict__ Wb, const float* __restrict__ bb,   // [NHID][32], [32]
    float* __restrict__ outT)
{
    constexpr int KV  = KIN / 4;
    constexpr int NCH = NHID / 32;
    const float4* __restrict__ Ain = FINAL ? g_A1 : g_A0;

    extern __shared__ __align__(16) float sm[];
    float* s_act = sm;                       // KIN*256
    float* s_h   = s_act + KIN * 256;        // 32*256
    float* s_wa  = s_h + 32 * 256;           // KIN*32
    float* s_wb  = s_wa + KIN * 32;          // 32*32
    float* s_ba  = s_wb + 32 * 32;           // 32

    int tid = threadIdx.x;
    int w = tid >> 5, lid = tid & 31;
    int node0 = blockIdx.x * 4;
    int rbase = slab * 64;

    // local row l (0..255) -> global row
    auto grow = [&](int l) -> size_t {
        return (size_t)(node0 + (l >> 6)) * BT + rbase + (l & 63);
    };

    // ---- stage 256 slab rows (2 rows/thread) -> k-major smem ----
#pragma unroll
    for (int g = 0; g < 2; g++) {
        int l = tid + g * 128;
        float4 a[KV];
        size_t ro = grow(l) * KV;
#pragma unroll
        for (int q = 0; q < KV; q++) a[q] = Ain[ro + q];
#pragma unroll
        for (int q = 0; q < KV; q++) {
            s_act[(4 * q + 0) * 256 + l] = a[q].x;
            s_act[(4 * q + 1) * 256 + l] = a[q].y;
            s_act[(4 * q + 2) * 256 + l] = a[q].z;
            s_act[(4 * q + 3) * 256 + l] = a[q].w;
        }
    }

    int jo = w * 8;
    int r4 = lid * 4;

    unsigned long long acc2[8][4];
#pragma unroll
    for (int o = 0; o < 8; o++) {
        float bv = bb[jo + o];
        unsigned long long bp = pk2(bv, bv);
#pragma unroll
        for (int p = 0; p < 4; p++) acc2[o][p] = bp;
    }

    for (int c = 0; c < NCH; c++) {
        __syncthreads();
        {
            const float4* Wav = (const float4*)Wa;
            for (int i = tid; i < KIN * 8; i += 128) {
                int k = i >> 3, jv = i & 7;
                ((float4*)s_wa)[k * 8 + jv] = Wav[k * (NHID / 4) + c * 8 + jv];
            }
            const float4* Wbv = (const float4*)Wb;
            for (int i = tid; i < 256; i += 128)
                ((float4*)s_wb)[i] = Wbv[c * 256 + i];
            if (tid < 32) s_ba[tid] = ba[c * 32 + tid];
        }
        __syncthreads();

        unsigned long long acc1[8][4];
#pragma unroll
        for (int o = 0; o < 8; o++) {
            float bv = s_ba[jo + o];
            unsigned long long bp = pk2(bv, bv);
#pragma unroll
            for (int p = 0; p < 4; p++) acc1[o][p] = bp;
        }
#pragma unroll 4
        for (int k = 0; k < KIN; k++) {
            ulonglong2 aA = *(const ulonglong2*)&s_act[k * 256 + r4];
            ulonglong2 aB = *(const ulonglong2*)&s_act[k * 256 + 128 + r4];
            float4 w0 = *(const float4*)&s_wa[k * 32 + jo];
            float4 w1 = *(const float4*)&s_wa[k * 32 + jo + 4];
            unsigned long long wd[8] = {pk2(w0.x, w0.x), pk2(w0.y, w0.y),
                                        pk2(w0.z, w0.z), pk2(w0.w, w0.w),
                                        pk2(w1.x, w1.x), pk2(w1.y, w1.y),
                                        pk2(w1.z, w1.z), pk2(w1.w, w1.w)};
#pragma unroll
            for (int o = 0; o < 8; o++) {
                acc1[o][0] = fma2(aA.x, wd[o], acc1[o][0]);
                acc1[o][1] = fma2(aA.y, wd[o], acc1[o][1]);
                acc1[o][2] = fma2(aB.x, wd[o], acc1[o][2]);
                acc1[o][3] = fma2(aB.y, wd[o], acc1[o][3]);
            }
        }
#pragma unroll
        for (int o = 0; o < 8; o++) {
            float2 p0 = upk2(acc1[o][0]), p1 = upk2(acc1[o][1]);
            float2 p2 = upk2(acc1[o][2]), p3 = upk2(acc1[o][3]);
            *(float4*)&s_h[(jo + o) * 256 + r4] =
                make_float4(fmaxf(p0.x, 0.f), fmaxf(p0.y, 0.f),
                            fmaxf(p1.x, 0.f), fmaxf(p1.y, 0.f));
            *(float4*)&s_h[(jo + o) * 256 + 128 + r4] =
                make_float4(fmaxf(p2.x, 0.f), fmaxf(p2.y, 0.f),
                            fmaxf(p3.x, 0.f), fmaxf(p3.y, 0.f));
        }
        __syncthreads();

#pragma unroll 4
        for (int kk = 0; kk < 32; kk++) {
            ulonglong2 aA = *(const ulonglong2*)&s_h[kk * 256 + r4];
            ulonglong2 aB = *(const ulonglong2*)&s_h[kk * 256 + 128 + r4];
            float4 w0 = *(const float4*)&s_wb[kk * 32 + jo];
            float4 w1 = *(const float4*)&s_wb[kk * 32 + jo + 4];
            unsigned long long wd[8] = {pk2(w0.x, w0.x), pk2(w0.y, w0.y),
                                        pk2(w0.z, w0.z), pk2(w0.w, w0.w),
                                        pk2(w1.x, w1.x), pk2(w1.y, w1.y),
                                        pk2(w1.z, w1.z), pk2(w1.w, w1.w)};
#pragma unroll
            for (int o = 0; o < 8; o++) {
                acc2[o][0] = fma2(aA.x, wd[o], acc2[o][0]);
                acc2[o][1] = fma2(aA.y, wd[o], acc2[o][1]);
                acc2[o][2] = fma2(aB.x, wd[o], acc2[o][2]);
                acc2[o][3] = fma2(aB.y, wd[o], acc2[o][3]);
            }
        }
    }

    // ---- epilogue ----
    if (!FINAL) {
        float4* Y = g_Y1;
#pragma unroll
        for (int g = 0; g < 2; g++) {
#pragma unroll
            for (int s = 0; s < 4; s++) {
                int p = g * 2 + (s >> 1);
                float f[8];
#pragma unroll
                for (int o = 0; o < 8; o++) {
                    float2 t = upk2(acc2[o][p]);
                    f[o] = (s & 1) ? t.y : t.x;
                }
                size_t bidx = grow(g * 128 + r4 + s) * 8 + w * 2;
                Y[bidx]     = make_float4(f[0], f[1], f[2], f[3]);
                Y[bidx + 1] = make_float4(f[4], f[5], f[6], f[7]);
            }
        }
    } else {
#pragma unroll
        for (int g = 0; g < 2; g++) {
#pragma unroll
            for (int s = 0; s < 4; s++) {
                int p = g * 2 + (s >> 1);
                int l = g * 128 + r4 + s;
                int n  = node0 + (l >> 6);
                int rr = rbase + (l & 63);
                int b = rr / TT, t = rr % TT;
                size_t ob = ((size_t)(b * NN + n) * CO + jo) * TT + t;
#pragma unroll
                for (int o = 0; o < 8; o++) {
                    float2 tv = upk2(acc2[o][p]);
                    float v = (s & 1) ? tv.y : tv.x;
                    outT[ob + (size_t)o * TT] = fmaxf(v, 0.f);
                }
            }
        }
    }
}

// ---------------- launch: 3 independent slab chains on 3 streams ----------------
extern "C" void kernel_launch(void* const* d_in, const int* in_sizes, int n_in,
                              void* d_out, int out_size) {
    const float* x  = (const float*)d_in[0];
    const void*  ei = d_in[1];
    const float* W1 = (const float*)d_in[2];
    const float* b1 = (const float*)d_in[3];
    const float* W2 = (const float*)d_in[4];
    const float* b2 = (const float*)d_in[5];
    const float* W3 = (const float*)d_in[6];
    const float* b3 = (const float*)d_in[7];
    const float* W4 = (const float*)d_in[8];
    const float* b4 = (const float*)d_in[9];
    float* out = (float*)d_out;

    const int SMEM1 = (CI * 256 + 32 * 256 + CI * 32 + 32 * 32 + 32) * 4;  // 55,424 B
    const int SMEM2 = (CO * 256 + 32 * 256 + CO * 32 + 32 * 32 + 32) * 4;  // 73,856 B

    static cudaStream_t st[3];
    static cudaEvent_t evIn, evPrep, evRoot, evS[3];
    static bool inited = false;
    if (!inited) {
        for (int i = 0; i < 3; i++) cudaStreamCreateWithFlags(&st[i], cudaStreamNonBlocking);
        cudaEventCreateWithFlags(&evIn,   cudaEventDisableTiming);
        cudaEventCreateWithFlags(&evPrep, cudaEventDisableTiming);
        cudaEventCreateWithFlags(&evRoot, cudaEventDisableTiming);
        for (int i = 0; i < 3; i++) cudaEventCreateWithFlags(&evS[i], cudaEventDisableTiming);
        cudaFuncSetAttribute(k_mlp<CI, 64, false>,
                             cudaFuncAttributeMaxDynamicSharedMemorySize, SMEM1);
        cudaFuncSetAttribute(k_mlp<CO, 128, true>,
                             cudaFuncAttributeMaxDynamicSharedMemorySize, SMEM2);
        inited = true;
    }

    // prepfill (1 block) on st[0] overlapped with transpose on default stream
    cudaEventRecord(evIn, 0);
    cudaStreamWaitEvent(st[0], evIn, 0);
    k_prepfill<<<1, 1024, 0, st[0]>>>(ei);
    cudaEventRecord(evPrep, st[0]);
    k_transpose<<<NN, 256>>>(x);
    cudaStreamWaitEvent(0, evPrep, 0);

    // fork: one chain per 64-row slab
    cudaEventRecord(evRoot, 0);
    for (int s = 0; s < 3; s++) {
        cudaStreamWaitEvent(st[s], evRoot, 0);
        k_gather<false><<<dim3(NN, 1), 256, 0, st[s]>>>(s * 256);
        k_mlp<CI, 64, false><<<NN / 4, 128, SMEM1, st[s]>>>(s, W1, b1, W2, b2, nullptr);
        k_gather<true><<<dim3(NN, 2), 256, 0, st[s]>>>(s * 512);
        k_mlp<CO, 128, true><<<NN / 4, 128, SMEM2, st[s]>>>(s, W3, b3, W4, b4, out);
        cudaEventRecord(evS[s], st[s]);
    }
    for (int s = 0; s < 3; s++) cudaStreamWaitEvent(0, evS[s], 0);
}

// round 16
// speedup vs baseline: 1.5318x; 1.0875x over previous
#include <cuda_runtime.h>

#define NB 8
#define NN 10000
#define CI 16
#define TT 24
#define CO 32
#define NE 160000
#define BT 192   // NB*TT

// ---------------- device scratch (float4-typed => 16B alignment) ----------------
__device__ float4 g_X0[(size_t)NN * BT * CI / 4];
__device__ float4 g_A0[(size_t)NN * BT * CI / 4];
__device__ float4 g_Y1[(size_t)NN * BT * CO / 4];
__device__ float4 g_A1[(size_t)NN * BT * CO / 4];
__device__ int    g_rowptr[NN + 1];
__device__ int    g_col[NE];
__device__ int    g_is64;

// ---------------- packed f32x2 helpers ----------------
__device__ __forceinline__ unsigned long long fma2(unsigned long long a,
                                                   unsigned long long b,
                                                   unsigned long long c) {
    unsigned long long d;
    asm("fma.rn.f32x2 %0, %1, %2, %3;" : "=l"(d) : "l"(a), "l"(b), "l"(c));
    return d;
}
__device__ __forceinline__ unsigned long long pk2(float x, float y) {
    unsigned long long r;
    asm("mov.b64 %0, {%1, %2};" : "=l"(r) : "f"(x), "f"(y));
    return r;
}
__device__ __forceinline__ float2 upk2(unsigned long long a) {
    float2 r;
    asm("mov.b64 {%0, %1}, %2;" : "=f"(r.x), "=f"(r.y) : "l"(a));
    return r;
}
__device__ __forceinline__ unsigned f2tf(float f) {
    unsigned r;
    asm("cvt.rna.tf32.f32 %0, %1;" : "=r"(r) : "f"(f));
    return r;
}
// tf32 warp MMA m16n8k8 (baseline PTX, sm_80+; HMMA path on sm_103)
__device__ __forceinline__ void mma_tf32(float* d, const unsigned* a,
                                         unsigned b0, unsigned b1) {
    asm volatile(
        "mma.sync.aligned.m16n8k8.row.col.f32.tf32.tf32.f32 "
        "{%0,%1,%2,%3}, {%4,%5,%6,%7}, {%8,%9}, {%0,%1,%2,%3};"
        : "+f"(d[0]), "+f"(d[1]), "+f"(d[2]), "+f"(d[3])
        : "r"(a[0]), "r"(a[1]), "r"(a[2]), "r"(a[3]), "r"(b0), "r"(b1));
}

__device__ __forceinline__ int edge_at(const void* ei, int idx) {
    if (g_is64) return (int)((const long long*)ei)[idx];
    return ((const int*)ei)[idx];
}

// ---------------- CSR prep+fill (unchanged) ----------------
__global__ void __launch_bounds__(1024) k_prepfill(const void* ei) {
    __shared__ int sdeg[NN];
    __shared__ int ssum[1024];
    int tid = threadIdx.x;
    if (tid == 0) {
        const long long* p = (const long long*)ei;
        int ok64 = 1;
        for (int q = 0; q < 64; q++) {
            long long v = p[q];
            if (v < 0 || v >= NN) { ok64 = 0; break; }
        }
        g_is64 = ok64;
    }
    __syncthreads();
    for (int i = tid; i < NN; i += 1024) sdeg[i] = 0;
    __syncthreads();
    for (int e = tid; e < NE; e += 1024) atomicAdd(&sdeg[edge_at(ei, NE + e)], 1);
    __syncthreads();
    const int CHUNK = 10;
    int start = tid * CHUNK;
    int s = 0;
    for (int i = start; i < start + CHUNK && i < NN; i++) s += sdeg[i];
    ssum[tid] = s;
    __syncthreads();
    for (int off = 1; off < 1024; off <<= 1) {
        int v = (tid >= off) ? ssum[tid - off] : 0;
        __syncthreads();
        ssum[tid] += v;
        __syncthreads();
    }
    int run = ssum[tid] - s;
    for (int i = start; i < start + CHUNK && i < NN; i++) {
        g_rowptr[i] = run;
        run += sdeg[i];
    }
    if (tid == 1023) g_rowptr[NN] = ssum[1023];
    __syncthreads();
    for (int i = tid; i < NN; i += 1024) sdeg[i] = 0;
    __syncthreads();
    for (int e = tid; e < NE; e += 1024) {
        int srcn = edge_at(ei, e);
        int d    = edge_at(ei, NE + e);
        int p = atomicAdd(&sdeg[d], 1);
        g_col[g_rowptr[d] + p] = srcn;
    }
}

// ---------------- input transpose (unchanged) ----------------
__global__ void k_transpose(const float* __restrict__ x) {
    __shared__ float s[BT * 17];
    int n = blockIdx.x;
    for (int j = threadIdx.x; j < NB * CI * TT; j += blockDim.x) {
        int b = j / (CI * TT);
        int r = j % (CI * TT);
        int c = r / TT;
        int t = r % TT;
        s[(b * TT + t) * 17 + c] = x[((size_t)(b * NN + n)) * (CI * TT) + r];
    }
    __syncthreads();
    float* X0f = (float*)g_X0;
    for (int j = threadIdx.x; j < BT * CI; j += blockDim.x) {
        X0f[(size_t)n * (BT * CI) + j] = s[(j >> 4) * 17 + (j & 15)];
    }
}

// ---------------- pure gather (unchanged) ----------------
template<bool L2PASS>
__global__ void __launch_bounds__(256) k_gather(int jbase) {
    constexpr int NF4 = L2PASS ? (BT * CO / 4) : (BT * CI / 4);
    const float4* __restrict__ Xin = L2PASS ? g_Y1 : g_X0;
    float4* __restrict__ Aout = L2PASS ? g_A1 : g_A0;

    int n = blockIdx.x;
    int j = jbase + blockIdx.y * 256 + threadIdx.x;
    size_t base = (size_t)n * NF4 + j;
    float4 acc = Xin[base];
    float4 acc2 = make_float4(0.f, 0.f, 0.f, 0.f);
    int rs = g_rowptr[n], re = g_rowptr[n + 1];
    int e = rs;
    for (; e + 1 < re; e += 2) {
        float4 v0 = Xin[(size_t)g_col[e] * NF4 + j];
        float4 v1 = Xin[(size_t)g_col[e + 1] * NF4 + j];
        acc.x += v0.x;  acc.y += v0.y;  acc.z += v0.z;  acc.w += v0.w;
        acc2.x += v1.x; acc2.y += v1.y; acc2.z += v1.z; acc2.w += v1.w;
    }
    if (e < re) {
        float4 v = Xin[(size_t)g_col[e] * NF4 + j];
        acc.x += v.x; acc.y += v.y; acc.z += v.z; acc.w += v.w;
    }
    acc.x += acc2.x; acc.y += acc2.y; acc.z += acc2.z; acc.w += acc2.w;
    Aout[base] = acc;
}

// ---------------- layer-1 MLP: f32x2, slab version (round-14, unchanged) ----------------
__global__ void __launch_bounds__(128) k_mlp1(
    int slab,
    const float* __restrict__ Wa, const float* __restrict__ ba,
    const float* __restrict__ Wb, const float* __restrict__ bb)
{
    constexpr int KIN = CI, NHID = 64, KV = KIN / 4, NCH = NHID / 32;

    extern __shared__ __align__(16) float sm[];
    float* s_act = sm;
    float* s_h   = s_act + KIN * 256;
    float* s_wa  = s_h + 32 * 256;
    float* s_wb  = s_wa + KIN * 32;
    float* s_ba  = s_wb + 32 * 32;

    int tid = threadIdx.x;
    int w = tid >> 5, lid = tid & 31;
    int node0 = blockIdx.x * 4;
    int rbase = slab * 64;
    auto grow = [&](int l) -> size_t {
        return (size_t)(node0 + (l >> 6)) * BT + rbase + (l & 63);
    };

#pragma unroll
    for (int g = 0; g < 2; g++) {
        int l = tid + g * 128;
        float4 a[KV];
        size_t ro = grow(l) * KV;
#pragma unroll
        for (int q = 0; q < KV; q++) a[q] = g_A0[ro + q];
#pragma unroll
        for (int q = 0; q < KV; q++) {
            s_act[(4 * q + 0) * 256 + l] = a[q].x;
            s_act[(4 * q + 1) * 256 + l] = a[q].y;
            s_act[(4 * q + 2) * 256 + l] = a[q].z;
            s_act[(4 * q + 3) * 256 + l] = a[q].w;
        }
    }

    int jo = w * 8;
    int r4 = lid * 4;

    unsigned long long acc2[8][4];
#pragma unroll
    for (int o = 0; o < 8; o++) {
        float bv = bb[jo + o];
        unsigned long long bp = pk2(bv, bv);
#pragma unroll
        for (int p = 0; p < 4; p++) acc2[o][p] = bp;
    }

    for (int c = 0; c < NCH; c++) {
        __syncthreads();
        {
            const float4* Wav = (const float4*)Wa;
            for (int i = tid; i < KIN * 8; i += 128) {
                int k = i >> 3, jv = i & 7;
                ((float4*)s_wa)[k * 8 + jv] = Wav[k * (NHID / 4) + c * 8 + jv];
            }
            const float4* Wbv = (const float4*)Wb;
            for (int i = tid; i < 256; i += 128)
                ((float4*)s_wb)[i] = Wbv[c * 256 + i];
            if (tid < 32) s_ba[tid] = ba[c * 32 + tid];
        }
        __syncthreads();

        unsigned long long acc1[8][4];
#pragma unroll
        for (int o = 0; o < 8; o++) {
            float bv = s_ba[jo + o];
            unsigned long long bp = pk2(bv, bv);
#pragma unroll
            for (int p = 0; p < 4; p++) acc1[o][p] = bp;
        }
#pragma unroll 4
        for (int k = 0; k < KIN; k++) {
            ulonglong2 aA = *(const ulonglong2*)&s_act[k * 256 + r4];
            ulonglong2 aB = *(const ulonglong2*)&s_act[k * 256 + 128 + r4];
            float4 w0 = *(const float4*)&s_wa[k * 32 + jo];
            float4 w1 = *(const float4*)&s_wa[k * 32 + jo + 4];
            unsigned long long wd[8] = {pk2(w0.x, w0.x), pk2(w0.y, w0.y),
                                        pk2(w0.z, w0.z), pk2(w0.w, w0.w),
                                        pk2(w1.x, w1.x), pk2(w1.y, w1.y),
                                        pk2(w1.z, w1.z), pk2(w1.w, w1.w)};
#pragma unroll
            for (int o = 0; o < 8; o++) {
                acc1[o][0] = fma2(aA.x, wd[o], acc1[o][0]);
                acc1[o][1] = fma2(aA.y, wd[o], acc1[o][1]);
                acc1[o][2] = fma2(aB.x, wd[o], acc1[o][2]);
                acc1[o][3] = fma2(aB.y, wd[o], acc1[o][3]);
            }
        }
#pragma unroll
        for (int o = 0; o < 8; o++) {
            float2 p0 = upk2(acc1[o][0]), p1 = upk2(acc1[o][1]);
            float2 p2 = upk2(acc1[o][2]), p3 = upk2(acc1[o][3]);
            *(float4*)&s_h[(jo + o) * 256 + r4] =
                make_float4(fmaxf(p0.x, 0.f), fmaxf(p0.y, 0.f),
                            fmaxf(p1.x, 0.f), fmaxf(p1.y, 0.f));
            *(float4*)&s_h[(jo + o) * 256 + 128 + r4] =
                make_float4(fmaxf(p2.x, 0.f), fmaxf(p2.y, 0.f),
                            fmaxf(p3.x, 0.f), fmaxf(p3.y, 0.f));
        }
        __syncthreads();

#pragma unroll 4
        for (int kk = 0; kk < 32; kk++) {
            ulonglong2 aA = *(const ulonglong2*)&s_h[kk * 256 + r4];
            ulonglong2 aB = *(const ulonglong2*)&s_h[kk * 256 + 128 + r4];
            float4 w0 = *(const float4*)&s_wb[kk * 32 + jo];
            float4 w1 = *(const float4*)&s_wb[kk * 32 + jo + 4];
            unsigned long long wd[8] = {pk2(w0.x, w0.x), pk2(w0.y, w0.y),
                                        pk2(w0.z, w0.z), pk2(w0.w, w0.w),
                                        pk2(w1.x, w1.x), pk2(w1.y, w1.y),
                                        pk2(w1.z, w1.z), pk2(w1.w, w1.w)};
#pragma unroll
            for (int o = 0; o < 8; o++) {
                acc2[o][0] = fma2(aA.x, wd[o], acc2[o][0]);
                acc2[o][1] = fma2(aA.y, wd[o], acc2[o][1]);
                acc2[o][2] = fma2(aB.x, wd[o], acc2[o][2]);
                acc2[o][3] = fma2(aB.y, wd[o], acc2[o][3]);
            }
        }
    }

    float4* Y = g_Y1;
#pragma unroll
    for (int g = 0; g < 2; g++) {
#pragma unroll
        for (int s = 0; s < 4; s++) {
            int p = g * 2 + (s >> 1);
            float f[8];
#pragma unroll
            for (int o = 0; o < 8; o++) {
                float2 t = upk2(acc2[o][p]);
                f[o] = (s & 1) ? t.y : t.x;
            }
            size_t bidx = grow(g * 128 + r4 + s) * 8 + w * 2;
            Y[bidx]     = make_float4(f[0], f[1], f[2], f[3]);
            Y[bidx + 1] = make_float4(f[4], f[5], f[6], f[7]);
        }
    }
}

// ================= layer-2 MLP via warp mma.sync tf32 (m16n8k8) =================
// Block = 128 thr = 4 warps = one (node, slab) = 64 rows; warp owns 16 rows.
// GEMM1: A(16x32) @ W3-chunk(32x64) -> acc1 (8 n8-tiles); relu+bias -> H (warp-private
// smem, tf32); GEMM2: H(16x64) @ W4-chunk(64x32) accumulates acc2 (4 n8-tiles).
// Pads: A 36, W3 132, W4 36, H 68 (all == 4 mod 32 -> conflict-free fragment LDS).
#define M2_SMEM ((64 * 36 + 32 * 132 + 128 * 36 + 64 * 68 + 128 + 32) * 4)

__global__ void __launch_bounds__(128) k_mlp2_mma(
    int slab,
    const float* __restrict__ W3, const float* __restrict__ b3,
    const float* __restrict__ W4, const float* __restrict__ b4,
    float* __restrict__ outT)
{
    extern __shared__ __align__(16) float sm2[];
    unsigned* uA  = (unsigned*)sm2;                 // 64*36
    unsigned* uW3 = uA + 64 * 36;                   // 32*132
    unsigned* uW4 = uW3 + 32 * 132;                 // 128*36
    unsigned* uH  = uW4 + 128 * 36;                 // 64*68
    float* sb3 = (float*)(uH + 64 * 68);            // 128
    float* sb4 = sb3 + 128;                         // 32

    int tid = threadIdx.x;
    int w = tid >> 5, lane = tid & 31;
    int g = lane >> 2, c = lane & 3;
    int n = blockIdx.x;
    int rbase = slab * 64;
    int m0 = w * 16;

    // ---- stage A (64 rows x 32), tf32, pad 36; 2 threads/row ----
    {
        int row = tid >> 1, half = tid & 1;
        size_t ro = ((size_t)n * BT + rbase + row) * 8 + half * 4;
        uint4* dst = (uint4*)(uA + row * 36 + half * 16);
#pragma unroll
        for (int q = 0; q < 4; q++) {
            float4 v = g_A1[ro + q];
            dst[q] = make_uint4(f2tf(v.x), f2tf(v.y), f2tf(v.z), f2tf(v.w));
        }
    }
    // ---- stage W3 [32][128] pad 132, W4 [128][32] pad 36, biases ----
    for (int i = tid; i < 4096; i += 128) {
        int r = i >> 7, col = i & 127;
        uW3[r * 132 + col] = f2tf(W3[i]);
    }
    for (int i = tid; i < 4096; i += 128) {
        int r = i >> 5, col = i & 31;
        uW4[r * 36 + col] = f2tf(W4[i]);
    }
    if (tid < 128) sb3[tid] = b3[tid];
    if (tid < 32)  sb4[tid] = b4[tid];
    __syncthreads();

    // ---- preload A fragments (k-steps 0..3) ----
    unsigned af[4][4];
#pragma unroll
    for (int kk = 0; kk < 4; kk++) {
        af[kk][0] = uA[(m0 + g)     * 36 + 8 * kk + c];
        af[kk][1] = uA[(m0 + g + 8) * 36 + 8 * kk + c];
        af[kk][2] = uA[(m0 + g)     * 36 + 8 * kk + c + 4];
        af[kk][3] = uA[(m0 + g + 8) * 36 + 8 * kk + c + 4];
    }

    float acc2[4][4];
#pragma unroll
    for (int j = 0; j < 4; j++)
#pragma unroll
        for (int p = 0; p < 4; p++) acc2[j][p] = 0.f;

#pragma unroll
    for (int ch = 0; ch < 2; ch++) {
        // ---- GEMM1: 8 hidden n8-tiles ----
        float acc1[8][4];
#pragma unroll
        for (int j = 0; j < 8; j++)
#pragma unroll
            for (int p = 0; p < 4; p++) acc1[j][p] = 0.f;
#pragma unroll
        for (int j = 0; j < 8; j++) {
#pragma unroll
            for (int kk = 0; kk < 4; kk++) {
                unsigned b0 = uW3[(8 * kk + c)     * 132 + ch * 64 + 8 * j + g];
                unsigned b1 = uW3[(8 * kk + c + 4) * 132 + ch * 64 + 8 * j + g];
                mma_tf32(acc1[j], af[kk], b0, b1);
            }
        }
        // ---- bias + relu + tf32 -> H (warp-private rows) ----
        __syncwarp();
#pragma unroll
        for (int j = 0; j < 8; j++) {
            int col0 = 8 * j + 2 * c;
            float v0 = fmaxf(acc1[j][0] + sb3[ch * 64 + col0],     0.f);
            float v1 = fmaxf(acc1[j][1] + sb3[ch * 64 + col0 + 1], 0.f);
            float v2 = fmaxf(acc1[j][2] + sb3[ch * 64 + col0],     0.f);
            float v3 = fmaxf(acc1[j][3] + sb3[ch * 64 + col0 + 1], 0.f);
            uH[(m0 + g)     * 68 + col0]     = f2tf(v0);
            uH[(m0 + g)     * 68 + col0 + 1] = f2tf(v1);
            uH[(m0 + g + 8) * 68 + col0]     = f2tf(v2);
            uH[(m0 + g + 8) * 68 + col0 + 1] = f2tf(v3);
        }
        __syncwarp();
        // ---- GEMM2: k = 64 (8 k-steps), 4 output n8-tiles ----
#pragma unroll
        for (int kk = 0; kk < 8; kk++) {
            unsigned a2[4];
            a2[0] = uH[(m0 + g)     * 68 + 8 * kk + c];
            a2[1] = uH[(m0 + g + 8) * 68 + 8 * kk + c];
            a2[2] = uH[(m0 + g)     * 68 + 8 * kk + c + 4];
            a2[3] = uH[(m0 + g + 8) * 68 + 8 * kk + c + 4];
#pragma unroll
            for (int j = 0; j < 4; j++) {
                unsigned b0 = uW4[(ch * 64 + 8 * kk + c)     * 36 + 8 * j + g];
                unsigned b1 = uW4[(ch * 64 + 8 * kk + c + 4) * 36 + 8 * j + g];
                mma_tf32(acc2[j], a2, b0, b1);
            }
        }
        __syncwarp();   // H reads done before next chunk overwrites (warp-local)
    }

    // ---- epilogue: bias + relu + transposed store ----
    {
        int rr0 = rbase + m0 + g;
        int rr1 = rr0 + 8;
        int b0r = rr0 / TT, t0 = rr0 % TT;
        int b1r = rr1 / TT, t1 = rr1 % TT;
        size_t ob0 = ((size_t)(b0r * NN + n) * CO) * TT + t0;
        size_t ob1 = ((size_t)(b1r * NN + n) * CO) * TT + t1;
#pragma unroll
        for (int j = 0; j < 4; j++) {
            int col0 = 8 * j + 2 * c;
            outT[ob0 + (size_t)col0 * TT]       = fmaxf(acc2[j][0] + sb4[col0],     0.f);
            outT[ob0 + (size_t)(col0 + 1) * TT] = fmaxf(acc2[j][1] + sb4[col0 + 1], 0.f);
            outT[ob1 + (size_t)col0 * TT]       = fmaxf(acc2[j][2] + sb4[col0],     0.f);
            outT[ob1 + (size_t)(col0 + 1) * TT] = fmaxf(acc2[j][3] + sb4[col0 + 1], 0.f);
        }
    }
}

// ---------------- launch: 3 slab chains on 3 streams ----------------
extern "C" void kernel_launch(void* const* d_in, const int* in_sizes, int n_in,
                              void* d_out, int out_size) {
    const float* x  = (const float*)d_in[0];
    const void*  ei = d_in[1];
    const float* W1 = (const float*)d_in[2];
    const float* b1 = (const float*)d_in[3];
    const float* W2 = (const float*)d_in[4];
    const float* b2 = (const float*)d_in[5];
    const float* W3 = (const float*)d_in[6];
    const float* b3 = (const float*)d_in[7];
    const float* W4 = (const float*)d_in[8];
    const float* b4 = (const float*)d_in[9];
    float* out = (float*)d_out;

    const int SMEM1 = (CI * 256 + 32 * 256 + CI * 32 + 32 * 32 + 32) * 4;  // 55,424 B

    static cudaStream_t st[3];
    static cudaEvent_t evIn, evPrep, evRoot, evS[3];
    static bool inited = false;
    if (!inited) {
        for (int i = 0; i < 3; i++) cudaStreamCreateWithFlags(&st[i], cudaStreamNonBlocking);
        cudaEventCreateWithFlags(&evIn,   cudaEventDisableTiming);
        cudaEventCreateWithFlags(&evPrep, cudaEventDisableTiming);
        cudaEventCreateWithFlags(&evRoot, cudaEventDisableTiming);
        for (int i = 0; i < 3; i++) cudaEventCreateWithFlags(&evS[i], cudaEventDisableTiming);
        cudaFuncSetAttribute(k_mlp1,
                             cudaFuncAttributeMaxDynamicSharedMemorySize, SMEM1);
        cudaFuncSetAttribute(k_mlp2_mma,
                             cudaFuncAttributeMaxDynamicSharedMemorySize, M2_SMEM);
        inited = true;
    }

    cudaEventRecord(evIn, 0);
    cudaStreamWaitEvent(st[0], evIn, 0);
    k_prepfill<<<1, 1024, 0, st[0]>>>(ei);
    cudaEventRecord(evPrep, st[0]);
    k_transpose<<<NN, 256>>>(x);
    cudaStreamWaitEvent(0, evPrep, 0);

    cudaEventRecord(evRoot, 0);
    for (int s = 0; s < 3; s++) {
        cudaStreamWaitEvent(st[s], evRoot, 0);
        k_gather<false><<<dim3(NN, 1), 256, 0, st[s]>>>(s * 256);
        k_mlp1<<<NN / 4, 128, SMEM1, st[s]>>>(s, W1, b1, W2, b2);
        k_gather<true><<<dim3(NN, 2), 256, 0, st[s]>>>(s * 512);
        k_mlp2_mma<<<NN, 128, M2_SMEM, st[s]>>>(s, W3, b3, W4, b4, out);
        cudaEventRecord(evS[s], st[s]);
    }
    for (int s = 0; s < 3; s++) cudaStreamWaitEvent(0, evS[s], 0);
}

// round 17
// speedup vs baseline: 1.6757x; 1.0940x over previous
#include <cuda_runtime.h>

#define NB 8
#define NN 10000
#define CI 16
#define TT 24
#define CO 32
#define NE 160000
#define BT 192   // NB*TT

// ---------------- device scratch (float4-typed => 16B alignment) ----------------
__device__ float4 g_X0[(size_t)NN * BT * CI / 4];
__device__ float4 g_A0[(size_t)NN * BT * CI / 4];
__device__ float4 g_Y1[(size_t)NN * BT * CO / 4];
__device__ float4 g_A1[(size_t)NN * BT * CO / 4];
__device__ int    g_rowptr[NN + 1];
__device__ int    g_col[NE];
__device__ int    g_is64;
// pre-converted tf32 weights in padded smem layout (row bytes % 16 == 0)
__device__ unsigned g_W3t[32 * 132];    // [k][j] pad 132
__device__ unsigned g_W4t[128 * 36];    // [k][o] pad 36

// ---------------- packed f32x2 helpers ----------------
__device__ __forceinline__ unsigned long long fma2(unsigned long long a,
                                                   unsigned long long b,
                                                   unsigned long long c) {
    unsigned long long d;
    asm("fma.rn.f32x2 %0, %1, %2, %3;" : "=l"(d) : "l"(a), "l"(b), "l"(c));
    return d;
}
__device__ __forceinline__ unsigned long long pk2(float x, float y) {
    unsigned long long r;
    asm("mov.b64 %0, {%1, %2};" : "=l"(r) : "f"(x), "f"(y));
    return r;
}
__device__ __forceinline__ float2 upk2(unsigned long long a) {
    float2 r;
    asm("mov.b64 {%0, %1}, %2;" : "=f"(r.x), "=f"(r.y) : "l"(a));
    return r;
}
__device__ __forceinline__ unsigned f2tf(float f) {
    unsigned r;
    asm("cvt.rna.tf32.f32 %0, %1;" : "=r"(r) : "f"(f));
    return r;
}
// tf32 warp MMA m16n8k8 (baseline PTX, sm_80+; HMMA path on sm_103)
__device__ __forceinline__ void mma_tf32(float* d, const unsigned* a,
                                         unsigned b0, unsigned b1) {
    asm volatile(
        "mma.sync.aligned.m16n8k8.row.col.f32.tf32.tf32.f32 "
        "{%0,%1,%2,%3}, {%4,%5,%6,%7}, {%8,%9}, {%0,%1,%2,%3};"
        : "+f"(d[0]), "+f"(d[1]), "+f"(d[2]), "+f"(d[3])
        : "r"(a[0]), "r"(a[1]), "r"(a[2]), "r"(a[3]), "r"(b0), "r"(b1));
}

__device__ __forceinline__ int edge_at(const void* ei, int idx) {
    if (g_is64) return (int)((const long long*)ei)[idx];
    return ((const int*)ei)[idx];
}

// ---------------- one-time weight conversion to padded tf32 ----------------
__global__ void k_wconv(const float* __restrict__ W3, const float* __restrict__ W4) {
    int i = blockIdx.x * blockDim.x + threadIdx.x;
    if (i < 4096) {
        int r = i >> 7, col = i & 127;
        g_W3t[r * 132 + col] = f2tf(W3[i]);
    } else if (i < 8192) {
        int j = i - 4096;
        int r = j >> 5, col = j & 31;
        g_W4t[r * 36 + col] = f2tf(W4[j]);
    }
}

// ---------------- CSR prep+fill (unchanged) ----------------
__global__ void __launch_bounds__(1024) k_prepfill(const void* ei) {
    __shared__ int sdeg[NN];
    __shared__ int ssum[1024];
    int tid = threadIdx.x;
    if (tid == 0) {
        const long long* p = (const long long*)ei;
        int ok64 = 1;
        for (int q = 0; q < 64; q++) {
            long long v = p[q];
            if (v < 0 || v >= NN) { ok64 = 0; break; }
        }
        g_is64 = ok64;
    }
    __syncthreads();
    for (int i = tid; i < NN; i += 1024) sdeg[i] = 0;
    __syncthreads();
    for (int e = tid; e < NE; e += 1024) atomicAdd(&sdeg[edge_at(ei, NE + e)], 1);
    __syncthreads();
    const int CHUNK = 10;
    int start = tid * CHUNK;
    int s = 0;
    for (int i = start; i < start + CHUNK && i < NN; i++) s += sdeg[i];
    ssum[tid] = s;
    __syncthreads();
    for (int off = 1; off < 1024; off <<= 1) {
        int v = (tid >= off) ? ssum[tid - off] : 0;
        __syncthreads();
        ssum[tid] += v;
        __syncthreads();
    }
    int run = ssum[tid] - s;
    for (int i = start; i < start + CHUNK && i < NN; i++) {
        g_rowptr[i] = run;
        run += sdeg[i];
    }
    if (tid == 1023) g_rowptr[NN] = ssum[1023];
    __syncthreads();
    for (int i = tid; i < NN; i += 1024) sdeg[i] = 0;
    __syncthreads();
    for (int e = tid; e < NE; e += 1024) {
        int srcn = edge_at(ei, e);
        int d    = edge_at(ei, NE + e);
        int p = atomicAdd(&sdeg[d], 1);
        g_col[g_rowptr[d] + p] = srcn;
    }
}

// ---------------- input transpose (unchanged) ----------------
__global__ void k_transpose(const float* __restrict__ x) {
    __shared__ float s[BT * 17];
    int n = blockIdx.x;
    for (int j = threadIdx.x; j < NB * CI * TT; j += blockDim.x) {
        int b = j / (CI * TT);
        int r = j % (CI * TT);
        int c = r / TT;
        int t = r % TT;
        s[(b * TT + t) * 17 + c] = x[((size_t)(b * NN + n)) * (CI * TT) + r];
    }
    __syncthreads();
    float* X0f = (float*)g_X0;
    for (int j = threadIdx.x; j < BT * CI; j += blockDim.x) {
        X0f[(size_t)n * (BT * CI) + j] = s[(j >> 4) * 17 + (j & 15)];
    }
}

// ---------------- pure gather (unchanged) ----------------
template<bool L2PASS>
__global__ void __launch_bounds__(256) k_gather(int jbase) {
    constexpr int NF4 = L2PASS ? (BT * CO / 4) : (BT * CI / 4);
    const float4* __restrict__ Xin = L2PASS ? g_Y1 : g_X0;
    float4* __restrict__ Aout = L2PASS ? g_A1 : g_A0;

    int n = blockIdx.x;
    int j = jbase + blockIdx.y * 256 + threadIdx.x;
    size_t base = (size_t)n * NF4 + j;
    float4 acc = Xin[base];
    float4 acc2 = make_float4(0.f, 0.f, 0.f, 0.f);
    int rs = g_rowptr[n], re = g_rowptr[n + 1];
    int e = rs;
    for (; e + 1 < re; e += 2) {
        float4 v0 = Xin[(size_t)g_col[e] * NF4 + j];
        float4 v1 = Xin[(size_t)g_col[e + 1] * NF4 + j];
        acc.x += v0.x;  acc.y += v0.y;  acc.z += v0.z;  acc.w += v0.w;
        acc2.x += v1.x; acc2.y += v1.y; acc2.z += v1.z; acc2.w += v1.w;
    }
    if (e < re) {
        float4 v = Xin[(size_t)g_col[e] * NF4 + j];
        acc.x += v.x; acc.y += v.y; acc.z += v.z; acc.w += v.w;
    }
    acc.x += acc2.x; acc.y += acc2.y; acc.z += acc2.z; acc.w += acc2.w;
    Aout[base] = acc;
}

// ---------------- layer-1 MLP: f32x2, slab version (unchanged) ----------------
__global__ void __launch_bounds__(128) k_mlp1(
    int slab,
    const float* __restrict__ Wa, const float* __restrict__ ba,
    const float* __restrict__ Wb, const float* __restrict__ bb)
{
    constexpr int KIN = CI, NHID = 64, KV = KIN / 4, NCH = NHID / 32;

    extern __shared__ __align__(16) float sm[];
    float* s_act = sm;
    float* s_h   = s_act + KIN * 256;
    float* s_wa  = s_h + 32 * 256;
    float* s_wb  = s_wa + KIN * 32;
    float* s_ba  = s_wb + 32 * 32;

    int tid = threadIdx.x;
    int w = tid >> 5, lid = tid & 31;
    int node0 = blockIdx.x * 4;
    int rbase = slab * 64;
    auto grow = [&](int l) -> size_t {
        return (size_t)(node0 + (l >> 6)) * BT + rbase + (l & 63);
    };

#pragma unroll
    for (int g = 0; g < 2; g++) {
        int l = tid + g * 128;
        float4 a[KV];
        size_t ro = grow(l) * KV;
#pragma unroll
        for (int q = 0; q < KV; q++) a[q] = g_A0[ro + q];
#pragma unroll
        for (int q = 0; q < KV; q++) {
            s_act[(4 * q + 0) * 256 + l] = a[q].x;
            s_act[(4 * q + 1) * 256 + l] = a[q].y;
            s_act[(4 * q + 2) * 256 + l] = a[q].z;
            s_act[(4 * q + 3) * 256 + l] = a[q].w;
        }
    }

    int jo = w * 8;
    int r4 = lid * 4;

    unsigned long long acc2[8][4];
#pragma unroll
    for (int o = 0; o < 8; o++) {
        float bv = bb[jo + o];
        unsigned long long bp = pk2(bv, bv);
#pragma unroll
        for (int p = 0; p < 4; p++) acc2[o][p] = bp;
    }

    for (int c = 0; c < NCH; c++) {
        __syncthreads();
        {
            const float4* Wav = (const float4*)Wa;
            for (int i = tid; i < KIN * 8; i += 128) {
                int k = i >> 3, jv = i & 7;
                ((float4*)s_wa)[k * 8 + jv] = Wav[k * (NHID / 4) + c * 8 + jv];
            }
            const float4* Wbv = (const float4*)Wb;
            for (int i = tid; i < 256; i += 128)
                ((float4*)s_wb)[i] = Wbv[c * 256 + i];
            if (tid < 32) s_ba[tid] = ba[c * 32 + tid];
        }
        __syncthreads();

        unsigned long long acc1[8][4];
#pragma unroll
        for (int o = 0; o < 8; o++) {
            float bv = s_ba[jo + o];
            unsigned long long bp = pk2(bv, bv);
#pragma unroll
            for (int p = 0; p < 4; p++) acc1[o][p] = bp;
        }
#pragma unroll 4
        for (int k = 0; k < KIN; k++) {
            ulonglong2 aA = *(const ulonglong2*)&s_act[k * 256 + r4];
            ulonglong2 aB = *(const ulonglong2*)&s_act[k * 256 + 128 + r4];
            float4 w0 = *(const float4*)&s_wa[k * 32 + jo];
            float4 w1 = *(const float4*)&s_wa[k * 32 + jo + 4];
            unsigned long long wd[8] = {pk2(w0.x, w0.x), pk2(w0.y, w0.y),
                                        pk2(w0.z, w0.z), pk2(w0.w, w0.w),
                                        pk2(w1.x, w1.x), pk2(w1.y, w1.y),
                                        pk2(w1.z, w1.z), pk2(w1.w, w1.w)};
#pragma unroll
            for (int o = 0; o < 8; o++) {
                acc1[o][0] = fma2(aA.x, wd[o], acc1[o][0]);
                acc1[o][1] = fma2(aA.y, wd[o], acc1[o][1]);
                acc1[o][2] = fma2(aB.x, wd[o], acc1[o][2]);
                acc1[o][3] = fma2(aB.y, wd[o], acc1[o][3]);
            }
        }
#pragma unroll
        for (int o = 0; o < 8; o++) {
            float2 p0 = upk2(acc1[o][0]), p1 = upk2(acc1[o][1]);
            float2 p2 = upk2(acc1[o][2]), p3 = upk2(acc1[o][3]);
            *(float4*)&s_h[(jo + o) * 256 + r4] =
                make_float4(fmaxf(p0.x, 0.f), fmaxf(p0.y, 0.f),
                            fmaxf(p1.x, 0.f), fmaxf(p1.y, 0.f));
            *(float4*)&s_h[(jo + o) * 256 + 128 + r4] =
                make_float4(fmaxf(p2.x, 0.f), fmaxf(p2.y, 0.f),
                            fmaxf(p3.x, 0.f), fmaxf(p3.y, 0.f));
        }
        __syncthreads();

#pragma unroll 4
        for (int kk = 0; kk < 32; kk++) {
            ulonglong2 aA = *(const ulonglong2*)&s_h[kk * 256 + r4];
            ulonglong2 aB = *(const ulonglong2*)&s_h[kk * 256 + 128 + r4];
            float4 w0 = *(const float4*)&s_wb[kk * 32 + jo];
            float4 w1 = *(const float4*)&s_wb[kk * 32 + jo + 4];
            unsigned long long wd[8] = {pk2(w0.x, w0.x), pk2(w0.y, w0.y),
                                        pk2(w0.z, w0.z), pk2(w0.w, w0.w),
                                        pk2(w1.x, w1.x), pk2(w1.y, w1.y),
                                        pk2(w1.z, w1.z), pk2(w1.w, w1.w)};
#pragma unroll
            for (int o = 0; o < 8; o++) {
                acc2[o][0] = fma2(aA.x, wd[o], acc2[o][0]);
                acc2[o][1] = fma2(aA.y, wd[o], acc2[o][1]);
                acc2[o][2] = fma2(aB.x, wd[o], acc2[o][2]);
                acc2[o][3] = fma2(aB.y, wd[o], acc2[o][3]);
            }
        }
    }

    float4* Y = g_Y1;
#pragma unroll
    for (int g = 0; g < 2; g++) {
#pragma unroll
        for (int s = 0; s < 4; s++) {
            int p = g * 2 + (s >> 1);
            float f[8];
#pragma unroll
            for (int o = 0; o < 8; o++) {
                float2 t = upk2(acc2[o][p]);
                f[o] = (s & 1) ? t.y : t.x;
            }
            size_t bidx = grow(g * 128 + r4 + s) * 8 + w * 2;
            Y[bidx]     = make_float4(f[0], f[1], f[2], f[3]);
            Y[bidx + 1] = make_float4(f[4], f[5], f[6], f[7]);
        }
    }
}

// ================= layer-2 MLP via warp mma.sync tf32: 2 nodes/block, 256 thr =================
// 8 warps; warp w owns 16 rows of the 128-row (2-node) tile. Weights copied from
// pre-converted padded tf32 globals with uint4 vector copies (no cvt in-block).
#define M2_SMEM ((128 * 36 + 32 * 132 + 128 * 36 + 128 * 68 + 128 + 32) * 4)

__global__ void __launch_bounds__(256) k_mlp2_mma(
    int slab,
    const float* __restrict__ b3, const float* __restrict__ b4,
    float* __restrict__ outT)
{
    extern __shared__ __align__(16) float sm2[];
    unsigned* uA  = (unsigned*)sm2;                 // 128*36
    unsigned* uW3 = uA + 128 * 36;                  // 32*132
    unsigned* uW4 = uW3 + 32 * 132;                 // 128*36
    unsigned* uH  = uW4 + 128 * 36;                 // 128*68
    float* sb3 = (float*)(uH + 128 * 68);           // 128
    float* sb4 = sb3 + 128;                         // 32

    int tid = threadIdx.x;
    int w = tid >> 5, lane = tid & 31;
    int g = lane >> 2, c = lane & 3;
    int node0 = blockIdx.x * 2;
    int rbase = slab * 64;
    int m0 = w * 16;

    // ---- stage A (128 rows x 32), tf32, pad 36; 2 threads/row ----
    {
        int row = tid >> 1, half = tid & 1;
        size_t ro = ((size_t)(node0 + (row >> 6)) * BT + rbase + (row & 63)) * 8 + half * 4;
        uint4* dst = (uint4*)(uA + row * 36 + half * 16);
#pragma unroll
        for (int q = 0; q < 4; q++) {
            float4 v = g_A1[ro + q];
            dst[q] = make_uint4(f2tf(v.x), f2tf(v.y), f2tf(v.z), f2tf(v.w));
        }
    }
    // ---- vector-copy pre-converted weights ----
    {
        const uint4* src3 = (const uint4*)g_W3t;   // 1056 uint4
        uint4* dst3 = (uint4*)uW3;
        for (int i = tid; i < 1056; i += 256) dst3[i] = src3[i];
        const uint4* src4 = (const uint4*)g_W4t;   // 1152 uint4
        uint4* dst4 = (uint4*)uW4;
        for (int i = tid; i < 1152; i += 256) dst4[i] = src4[i];
    }
    if (tid < 128) sb3[tid] = b3[tid];
    if (tid < 32)  sb4[tid] = b4[tid];
    __syncthreads();

    // ---- preload A fragments (k-steps 0..3) ----
    unsigned af[4][4];
#pragma unroll
    for (int kk = 0; kk < 4; kk++) {
        af[kk][0] = uA[(m0 + g)     * 36 + 8 * kk + c];
        af[kk][1] = uA[(m0 + g + 8) * 36 + 8 * kk + c];
        af[kk][2] = uA[(m0 + g)     * 36 + 8 * kk + c + 4];
        af[kk][3] = uA[(m0 + g + 8) * 36 + 8 * kk + c + 4];
    }

    float acc2[4][4];
#pragma unroll
    for (int j = 0; j < 4; j++)
#pragma unroll
        for (int p = 0; p < 4; p++) acc2[j][p] = 0.f;

#pragma unroll
    for (int ch = 0; ch < 2; ch++) {
        float acc1[8][4];
#pragma unroll
        for (int j = 0; j < 8; j++)
#pragma unroll
            for (int p = 0; p < 4; p++) acc1[j][p] = 0.f;
#pragma unroll
        for (int j = 0; j < 8; j++) {
#pragma unroll
            for (int kk = 0; kk < 4; kk++) {
                unsigned b0 = uW3[(8 * kk + c)     * 132 + ch * 64 + 8 * j + g];
                unsigned b1 = uW3[(8 * kk + c + 4) * 132 + ch * 64 + 8 * j + g];
                mma_tf32(acc1[j], af[kk], b0, b1);
            }
        }
        __syncwarp();
#pragma unroll
        for (int j = 0; j < 8; j++) {
            int col0 = 8 * j + 2 * c;
            float v0 = fmaxf(acc1[j][0] + sb3[ch * 64 + col0],     0.f);
            float v1 = fmaxf(acc1[j][1] + sb3[ch * 64 + col0 + 1], 0.f);
            float v2 = fmaxf(acc1[j][2] + sb3[ch * 64 + col0],     0.f);
            float v3 = fmaxf(acc1[j][3] + sb3[ch * 64 + col0 + 1], 0.f);
            uH[(m0 + g)     * 68 + col0]     = f2tf(v0);
            uH[(m0 + g)     * 68 + col0 + 1] = f2tf(v1);
            uH[(m0 + g + 8) * 68 + col0]     = f2tf(v2);
            uH[(m0 + g + 8) * 68 + col0 + 1] = f2tf(v3);
        }
        __syncwarp();
#pragma unroll
        for (int kk = 0; kk < 8; kk++) {
            unsigned a2[4];
            a2[0] = uH[(m0 + g)     * 68 + 8 * kk + c];
            a2[1] = uH[(m0 + g + 8) * 68 + 8 * kk + c];
            a2[2] = uH[(m0 + g)     * 68 + 8 * kk + c + 4];
            a2[3] = uH[(m0 + g + 8) * 68 + 8 * kk + c + 4];
#pragma unroll
            for (int j = 0; j < 4; j++) {
                unsigned b0 = uW4[(ch * 64 + 8 * kk + c)     * 36 + 8 * j + g];
                unsigned b1 = uW4[(ch * 64 + 8 * kk + c + 4) * 36 + 8 * j + g];
                mma_tf32(acc2[j], a2, b0, b1);
            }
        }
        __syncwarp();
    }

    // ---- epilogue: bias + relu + transposed store ----
    {
        int l0 = m0 + g;                 // 0..127
        int node = node0 + (l0 >> 6);
        int rr0 = rbase + (l0 & 63);
        int rr1 = rr0 + 8;               // same node (l0&63 <= 55)
        int b0r = rr0 / TT, t0 = rr0 % TT;
        int b1r = rr1 / TT, t1 = rr1 % TT;
        size_t ob0 = ((size_t)(b0r * NN + node) * CO) * TT + t0;
        size_t ob1 = ((size_t)(b1r * NN + node) * CO) * TT + t1;
#pragma unroll
        for (int j = 0; j < 4; j++) {
            int col0 = 8 * j + 2 * c;
            outT[ob0 + (size_t)col0 * TT]       = fmaxf(acc2[j][0] + sb4[col0],     0.f);
            outT[ob0 + (size_t)(col0 + 1) * TT] = fmaxf(acc2[j][1] + sb4[col0 + 1], 0.f);
            outT[ob1 + (size_t)col0 * TT]       = fmaxf(acc2[j][2] + sb4[col0],     0.f);
            outT[ob1 + (size_t)(col0 + 1) * TT] = fmaxf(acc2[j][3] + sb4[col0 + 1], 0.f);
        }
    }
}

// ---------------- launch: 3 slab chains on 3 streams ----------------
extern "C" void kernel_launch(void* const* d_in, const int* in_sizes, int n_in,
                              void* d_out, int out_size) {
    const float* x  = (const float*)d_in[0];
    const void*  ei = d_in[1];
    const float* W1 = (const float*)d_in[2];
    const float* b1 = (const float*)d_in[3];
    const float* W2 = (const float*)d_in[4];
    const float* b2 = (const float*)d_in[5];
    const float* W3 = (const float*)d_in[6];
    const float* b3 = (const float*)d_in[7];
    const float* W4 = (const float*)d_in[8];
    const float* b4 = (const float*)d_in[9];
    float* out = (float*)d_out;

    const int SMEM1 = (CI * 256 + 32 * 256 + CI * 32 + 32 * 32 + 32) * 4;  // 55,424 B

    static cudaStream_t st[3];
    static cudaEvent_t evIn, evPrep, evRoot, evS[3];
    static bool inited = false;
    if (!inited) {
        for (int i = 0; i < 3; i++) cudaStreamCreateWithFlags(&st[i], cudaStreamNonBlocking);
        cudaEventCreateWithFlags(&evIn,   cudaEventDisableTiming);
        cudaEventCreateWithFlags(&evPrep, cudaEventDisableTiming);
        cudaEventCreateWithFlags(&evRoot, cudaEventDisableTiming);
        for (int i = 0; i < 3; i++) cudaEventCreateWithFlags(&evS[i], cudaEventDisableTiming);
        cudaFuncSetAttribute(k_mlp1,
                             cudaFuncAttributeMaxDynamicSharedMemorySize, SMEM1);
        cudaFuncSetAttribute(k_mlp2_mma,
                             cudaFuncAttributeMaxDynamicSharedMemorySize, M2_SMEM);
        inited = true;
    }

    cudaEventRecord(evIn, 0);
    cudaStreamWaitEvent(st[0], evIn, 0);
    k_prepfill<<<1, 1024, 0, st[0]>>>(ei);
    k_wconv<<<32, 256, 0, st[0]>>>(W3, W4);
    cudaEventRecord(evPrep, st[0]);
    k_transpose<<<NN, 256>>>(x);
    cudaStreamWaitEvent(0, evPrep, 0);

    cudaEventRecord(evRoot, 0);
    for (int s = 0; s < 3; s++) {
        cudaStreamWaitEvent(st[s], evRoot, 0);
        k_gather<false><<<dim3(NN, 1), 256, 0, st[s]>>>(s * 256);
        k_mlp1<<<NN / 4, 128, SMEM1, st[s]>>>(s, W1, b1, W2, b2);
        k_gather<true><<<dim3(NN, 2), 256, 0, st[s]>>>(s * 512);
        k_mlp2_mma<<<NN / 2, 256, M2_SMEM, st[s]>>>(s, b3, b4, out);
        cudaEventRecord(evS[s], st[s]);
    }
    for (int s = 0; s < 3; s++) cudaStreamWaitEvent(0, evS[s], 0);
}